// round 1
// baseline (speedup 1.0000x reference)
#include <cuda_runtime.h>
#include <math.h>

// ---------------------------------------------------------------------------
// Problem constants (fixed shapes from reference):
//   B=2, T=8, H=W=56, C=512, HID=1024.  tokens NTOK = 50176.
// ---------------------------------------------------------------------------
#define NTOK 50176
#define TPB  25088      // tokens per batch (T*H*W)
#define Wd   56
#define Hd   56
#define CIN  512
#define HIDN 1024
#define RED_CHUNKS 49   // 25088 / 512

// Scratch (allocation-free rule: __device__ globals)
__device__ float g_xh  [(size_t)NTOK * HIDN];   // gelu(x@fc_w+b)      205 MB
__device__ float g_hpre[(size_t)NTOK * CIN];    // gelu(shift(xh)@fc1) 103 MB
__device__ float g_wbuf[(size_t)NTOK * CIN];    // gelu(xh@fc2)        103 MB
__device__ float g_part[2 * RED_CHUNKS * CIN];  // partial sums
__device__ float g_a01 [4 * CIN];               // a0[2][512], a1[2][512]

// SHIFTS table: (1,1),(1,0),(1,-1),(0,1),(0,0),(0,-1),(-1,1),(-1,0),(-1,-1)
__constant__ int c_sh[9] = { 1, 1, 1, 0, 0, 0,-1,-1,-1};
__constant__ int c_sw[9] = { 1, 0,-1, 1, 0,-1, 1, 0,-1};

__device__ __forceinline__ float gelu_exact(float v) {
    return 0.5f * v * (1.0f + erff(v * 0.70710678118654752f));
}

// ---------------------------------------------------------------------------
// Tiled SGEMM: C[M,N] = epilogue(A'[M,K] @ Bm[K,N] + bias)
//   MODE 0: A' = A (plain), epilogue = gelu
//   MODE 1: A' = forward patch_shift of A (group size 114, K=1024), gelu
//   MODE 2: A' = gather_inv(hpre)*a0 + wbuf*a1 (group 57, K=512), bias only
// Block tile 128x128, K-tile 8, 256 threads, 8x8 per thread.
// M=50176 (div 128), N in {512,1024} (div 128), K in {512,1024} (div 8):
// no bounds checks needed.
// ---------------------------------------------------------------------------
template <int MODE>
__global__ __launch_bounds__(256, 2)
void gemm_kernel(const float* __restrict__ A, const float* __restrict__ Bm,
                 const float* __restrict__ bias, float* __restrict__ C,
                 int N, int K,
                 const float* __restrict__ Wbuf, const float* __restrict__ Avec)
{
    __shared__ float As[8][128];
    __shared__ float Bs[8][128];

    const int tid = threadIdx.x;
    const int bm  = blockIdx.y * 128;
    const int bn  = blockIdx.x * 128;

    // A-tile load assignment: 1024 elements, 4 per thread.
    // element idx = tid + i*256 ; row = idx>>3 ; k-in-tile = idx&7 == tid&7
    const int kA = tid & 7;
    int rA[4], yA[4], xA[4], bA[4];
#pragma unroll
    for (int i = 0; i < 4; i++) {
        int r = ((tid + i * 256) >> 3);
        rA[i] = bm + r;
        if (MODE != 0) {
            int m = rA[i];
            yA[i] = (m / Wd) % Hd;
            xA[i] = m % Wd;
            bA[i] = m / TPB;
        }
    }
    // B-tile load: 256 float4, one per thread
    const int kB = tid >> 5;         // 0..7
    const int cB = (tid & 31) * 4;   // 0..124

    const int tm0 = (tid >> 4) * 8;
    const int tn0 = (tid & 15) * 8;

    float acc[8][8];
#pragma unroll
    for (int i = 0; i < 8; i++)
#pragma unroll
        for (int j = 0; j < 8; j++) acc[i][j] = 0.0f;

    for (int kt = 0; kt < K; kt += 8) {
        // ---- load A tile (scalar; gather-aware) ----
        const int gk = kt + kA;
#pragma unroll
        for (int i = 0; i < 4; i++) {
            int r = ((tid + i * 256) >> 3);
            float v;
            if (MODE == 0) {
                v = A[(size_t)rA[i] * K + gk];
            } else if (MODE == 1) {
                int g  = gk / 114;           // forward shift, group size 114
                int sh = c_sh[g], sw = c_sw[g];
                int ys = yA[i] - sh, xs = xA[i] - sw;
                v = 0.0f;
                if ((unsigned)ys < 56u && (unsigned)xs < 56u)
                    v = A[(size_t)(rA[i] - sh * Wd - sw) * K + gk];
            } else {
                int g  = gk / 57;            // inverse shift, group size 57
                int sh = c_sh[g], sw = c_sw[g];
                int ys = yA[i] + sh, xs = xA[i] + sw;
                float hv = 0.0f;
                if ((unsigned)ys < 56u && (unsigned)xs < 56u)
                    hv = A[(size_t)(rA[i] + sh * Wd + sw) * K + gk];
                float wv = Wbuf[(size_t)rA[i] * K + gk];
                float a0 = Avec[bA[i] * CIN + gk];
                float a1 = Avec[2 * CIN + bA[i] * CIN + gk];
                v = hv * a0 + wv * a1;
            }
            As[kA][r] = v;
        }
        // ---- load B tile (vectorized) ----
        const float4 bv = *(const float4*)&Bm[(size_t)(kt + kB) * N + bn + cB];
        *(float4*)&Bs[kB][cB] = bv;

        __syncthreads();

        // ---- compute ----
#pragma unroll
        for (int kk = 0; kk < 8; kk++) {
            float ar[8], br[8];
            *(float4*)&ar[0] = *(const float4*)&As[kk][tm0];
            *(float4*)&ar[4] = *(const float4*)&As[kk][tm0 + 4];
            *(float4*)&br[0] = *(const float4*)&Bs[kk][tn0];
            *(float4*)&br[4] = *(const float4*)&Bs[kk][tn0 + 4];
#pragma unroll
            for (int i = 0; i < 8; i++)
#pragma unroll
                for (int j = 0; j < 8; j++)
                    acc[i][j] = fmaf(ar[i], br[j], acc[i][j]);
        }
        __syncthreads();
    }

    // ---- epilogue ----
    float bcol[8];
#pragma unroll
    for (int j = 0; j < 8; j++) bcol[j] = bias[bn + tn0 + j];

#pragma unroll
    for (int i = 0; i < 8; i++) {
        const int row = bm + tm0 + i;
#pragma unroll
        for (int j = 0; j < 8; j += 4) {
            float4 o;
            o.x = acc[i][j + 0] + bcol[j + 0];
            o.y = acc[i][j + 1] + bcol[j + 1];
            o.z = acc[i][j + 2] + bcol[j + 2];
            o.w = acc[i][j + 3] + bcol[j + 3];
            if (MODE < 2) {
                o.x = gelu_exact(o.x);
                o.y = gelu_exact(o.y);
                o.z = gelu_exact(o.z);
                o.w = gelu_exact(o.w);
            }
            *(float4*)&C[(size_t)row * N + bn + tn0 + j] = o;
        }
    }
}

// ---------------------------------------------------------------------------
// Deterministic 2-stage mean over (T,H,W) of (h + w), h = inv-shift(hpre).
// Stage 1: grid (49, 2), 512 threads; each block sums 512 tokens x 512 ch.
// ---------------------------------------------------------------------------
__global__ void reduce_kernel(const float* __restrict__ hpre,
                              const float* __restrict__ wbuf,
                              float* __restrict__ part)
{
    const int c = threadIdx.x;       // channel 0..511
    const int b = blockIdx.y;        // batch
    const int chunk = blockIdx.x;    // 0..48
    const int g = c / 57;
    const int sh = c_sh[g], sw = c_sw[g];

    float acc = 0.0f;
    const int m0 = b * TPB + chunk * 512;
    for (int it = 0; it < 512; it++) {
        const int m = m0 + it;
        const int y = (m / Wd) % Hd;
        const int x = m % Wd;
        const int ys = y + sh, xs = x + sw;
        float hv = 0.0f;
        if ((unsigned)ys < 56u && (unsigned)xs < 56u)
            hv = hpre[(size_t)(m + sh * Wd + sw) * CIN + c];
        acc += hv + wbuf[(size_t)m * CIN + c];
    }
    part[(size_t)(b * RED_CHUNKS + chunk) * CIN + c] = acc;
}

// ---------------------------------------------------------------------------
// Head: finish mean, tiny MLP (512->128 gelu ->1024), pairwise softmax.
// Single block, 512 threads.
// ---------------------------------------------------------------------------
__global__ void head_kernel(const float* __restrict__ part,
                            const float* __restrict__ rw1_w,
                            const float* __restrict__ rw1_b,
                            const float* __restrict__ rw2_w,
                            const float* __restrict__ rw2_b,
                            float* __restrict__ a01)
{
    __shared__ float s_in[512];
    __shared__ float s_t1[128];
    __shared__ float s_t2[1024];
    const int tid = threadIdx.x;

    for (int b = 0; b < 2; b++) {
        float s = 0.0f;
        for (int p = 0; p < RED_CHUNKS; p++)
            s += part[(size_t)(b * RED_CHUNKS + p) * CIN + tid];
        s_in[tid] = s * (1.0f / (float)TPB);
        __syncthreads();

        if (tid < 128) {
            float acc = rw1_b[tid];
            for (int c = 0; c < 512; c++)
                acc = fmaf(s_in[c], rw1_w[c * 128 + tid], acc);
            s_t1[tid] = gelu_exact(acc);
        }
        __syncthreads();

        for (int n = tid; n < 1024; n += 512) {
            float acc = rw2_b[n];
            for (int j = 0; j < 128; j++)
                acc = fmaf(s_t1[j], rw2_w[j * 1024 + n], acc);
            s_t2[n] = acc;
        }
        __syncthreads();

        {
            const float v0 = s_t2[2 * tid];
            const float v1 = s_t2[2 * tid + 1];
            const float mx = fmaxf(v0, v1);
            const float e0 = expf(v0 - mx);
            const float e1 = expf(v1 - mx);
            const float inv = 1.0f / (e0 + e1);
            a01[b * CIN + tid]             = e0 * inv;  // a0
            a01[2 * CIN + b * CIN + tid]   = e1 * inv;  // a1
        }
        __syncthreads();
    }
}

// ---------------------------------------------------------------------------
extern "C" void kernel_launch(void* const* d_in, const int* in_sizes, int n_in,
                              void* d_out, int out_size)
{
    const float* x      = (const float*)d_in[0];
    const float* fc_w   = (const float*)d_in[1];
    const float* fc_b   = (const float*)d_in[2];
    const float* fc1_w  = (const float*)d_in[3];
    const float* fc1_b  = (const float*)d_in[4];
    const float* fc2_w  = (const float*)d_in[5];
    const float* fc2_b  = (const float*)d_in[6];
    const float* rw1_w  = (const float*)d_in[7];
    const float* rw1_b  = (const float*)d_in[8];
    const float* rw2_w  = (const float*)d_in[9];
    const float* rw2_b  = (const float*)d_in[10];
    const float* proj_w = (const float*)d_in[11];
    const float* proj_b = (const float*)d_in[12];
    float* out = (float*)d_out;

    float *xh, *hpre, *wbuf, *part, *a01;
    cudaGetSymbolAddress((void**)&xh,   g_xh);
    cudaGetSymbolAddress((void**)&hpre, g_hpre);
    cudaGetSymbolAddress((void**)&wbuf, g_wbuf);
    cudaGetSymbolAddress((void**)&part, g_part);
    cudaGetSymbolAddress((void**)&a01,  g_a01);

    const dim3 blk(256);
    const dim3 gridM_hid(HIDN / 128, NTOK / 128);
    const dim3 gridM_cin(CIN / 128, NTOK / 128);

    // 1) xh = gelu(x @ fc_w + fc_b)                       [50176,1024]
    gemm_kernel<0><<<gridM_hid, blk>>>(x, fc_w, fc_b, xh, HIDN, CIN,
                                       nullptr, nullptr);
    // 2) hpre = gelu(shift_fwd(xh) @ fc1_w + fc1_b)       [50176,512]
    gemm_kernel<1><<<gridM_cin, blk>>>(xh, fc1_w, fc1_b, hpre, CIN, HIDN,
                                       nullptr, nullptr);
    // 3) w = gelu(xh @ fc2_w + fc2_b)                     [50176,512]
    gemm_kernel<0><<<gridM_cin, blk>>>(xh, fc2_w, fc2_b, wbuf, CIN, HIDN,
                                       nullptr, nullptr);
    // 4) partial sums of (shift_inv(hpre) + w) over tokens
    reduce_kernel<<<dim3(RED_CHUNKS, 2), 512>>>(hpre, wbuf, part);
    // 5) head MLP + pairwise softmax -> a0, a1
    head_kernel<<<1, 512>>>(part, rw1_w, rw1_b, rw2_w, rw2_b, a01);
    // 6) out = (h*a0 + w*a1) @ proj_w + proj_b            [50176,512]
    gemm_kernel<2><<<gridM_cin, blk>>>(hpre, proj_w, proj_b, out, CIN, CIN,
                                       wbuf, a01);
}

// round 5
// speedup vs baseline: 2.8940x; 2.8940x over previous
#include <cuda_runtime.h>
#include <cuda_bf16.h>
#include <math.h>
#include <cstdint>

// ---------------------------------------------------------------------------
// Shapes: B=2, T=8, H=W=56, C=512, HID=1024. NTOK = 50176.
// ---------------------------------------------------------------------------
#define NTOK 50176
#define TPB  25088
#define Wd   56
#define CIN  512
#define HIDN 1024
#define RED_CHUNKS 49

// ---------------------------------------------------------------------------
// Scratch (__device__ globals; allocation-free rule). 128B aligned for cp.async.
// ---------------------------------------------------------------------------
__device__ __align__(128) __nv_bfloat16 g_xhi [(size_t)NTOK * CIN];
__device__ __align__(128) __nv_bfloat16 g_xlo [(size_t)NTOK * CIN];
__device__ __align__(128) __nv_bfloat16 g_xhhi[(size_t)NTOK * HIDN];
__device__ __align__(128) __nv_bfloat16 g_xhlo[(size_t)NTOK * HIDN];
__device__ __align__(128) __nv_bfloat16 g_xshi[(size_t)NTOK * HIDN];
__device__ __align__(128) __nv_bfloat16 g_xslo[(size_t)NTOK * HIDN];
__device__ __align__(128) float         g_hpre[(size_t)NTOK * CIN];
__device__ __align__(128) float         g_wbuf[(size_t)NTOK * CIN];
__device__ __align__(128) __nv_bfloat16 g_cmhi[(size_t)NTOK * CIN];
__device__ __align__(128) __nv_bfloat16 g_cmlo[(size_t)NTOK * CIN];
__device__ __align__(128) __nv_bfloat16 g_w1hi[HIDN * CIN],  g_w1lo[HIDN * CIN];
__device__ __align__(128) __nv_bfloat16 g_w2hi[CIN * HIDN],  g_w2lo[CIN * HIDN];
__device__ __align__(128) __nv_bfloat16 g_w3hi[CIN * HIDN],  g_w3lo[CIN * HIDN];
__device__ __align__(128) __nv_bfloat16 g_w4hi[CIN * CIN],   g_w4lo[CIN * CIN];
__device__ float g_part[2 * RED_CHUNKS * CIN];
__device__ float g_a01 [4 * CIN];

__constant__ int c_sh[9] = { 1, 1, 1, 0, 0, 0,-1,-1,-1};
__constant__ int c_sw[9] = { 1, 0,-1, 1, 0,-1, 1, 0,-1};

__device__ __forceinline__ float gelu_exact(float v) {
    return 0.5f * v * (1.0f + erff(v * 0.70710678118654752f));
}
__device__ __forceinline__ void split_bf16(float v, __nv_bfloat16& h, __nv_bfloat16& l) {
    h = __float2bfloat16(v);
    l = __float2bfloat16(v - __bfloat162float(h));
}
__device__ __forceinline__ uint32_t smem_u32(const void* p) {
    uint32_t a;
    asm("{ .reg .u64 t; cvta.to.shared.u64 t, %1; cvt.u32.u64 %0, t; }" : "=r"(a) : "l"(p));
    return a;
}

#define CP_ASYNC16(dst, src) \
    asm volatile("cp.async.cg.shared.global [%0], [%1], 16;" :: "r"(dst), "l"(src) : "memory")
#define CP_COMMIT() asm volatile("cp.async.commit_group;" ::: "memory")

#define LDSM4(r, a) \
    asm volatile("ldmatrix.sync.aligned.m8n8.x4.shared.b16 {%0,%1,%2,%3}, [%4];" \
        : "=r"((r)[0]), "=r"((r)[1]), "=r"((r)[2]), "=r"((r)[3]) : "r"(a))

#define MMA16816(d, a, b0, b1) \
    asm volatile("mma.sync.aligned.m16n8k16.row.col.f32.bf16.bf16.f32 " \
        "{%0,%1,%2,%3}, {%4,%5,%6,%7}, {%8,%9}, {%0,%1,%2,%3};" \
        : "+f"((d)[0]), "+f"((d)[1]), "+f"((d)[2]), "+f"((d)[3]) \
        : "r"((a)[0]), "r"((a)[1]), "r"((a)[2]), "r"((a)[3]), "r"(b0), "r"(b1))

// ---------------------------------------------------------------------------
// HMMA GEMM: C[M,N] = epi(A@W + bias), A = Ahi+Alo [M,K], W^T = Bhi+Blo [N,K].
// CTA 128x128, warp grid 4(m) x 2(n), warp tile 32x64, K-chunk 64, 3 stages.
// EPI 0: gelu -> split bf16.  EPI 1: gelu -> f32.  EPI 2: bias only -> f32.
// ---------------------------------------------------------------------------
#define STAGE_BYTES 65536
#define GEMM_SMEM   (3 * STAGE_BYTES)

template <int EPI>
__global__ __launch_bounds__(256, 1)
void mma_gemm(const __nv_bfloat16* __restrict__ Ahi, const __nv_bfloat16* __restrict__ Alo,
              const __nv_bfloat16* __restrict__ Bhi, const __nv_bfloat16* __restrict__ Blo,
              const float* __restrict__ bias, int N, int K,
              float* __restrict__ Cf, __nv_bfloat16* __restrict__ Chi,
              __nv_bfloat16* __restrict__ Clo)
{
    extern __shared__ char smraw[];
    const uint32_t smb = smem_u32(smraw);

    const int tid  = threadIdx.x;
    const int wid  = tid >> 5;
    const int lane = tid & 31;
    const int wm   = wid & 3;        // 0..3 -> m offset wm*32
    const int wn   = wid >> 2;       // 0..1 -> n offset wn*64
    const int bm   = blockIdx.y * 128;
    const int bn   = blockIdx.x * 128;

    const __nv_bfloat16* p0 = Ahi + (size_t)bm * K;
    const __nv_bfloat16* p1 = Alo + (size_t)bm * K;
    const __nv_bfloat16* p2 = Bhi + (size_t)bn * K;
    const __nv_bfloat16* p3 = Blo + (size_t)bn * K;

    // loader geometry (16 x cp.async 16B per thread per chunk)
    const int ldRow = tid >> 3;          // 0..31 (+32*(t&3))
    const int ldChk = tid & 7;

    // ldmatrix lane geometry
    const int lrowA = lane & 15;                       // A: rows 0..15
    const int lckA  = lane >> 4;                       // A: k-half
    const int lrowB = (lane & 7) + ((lane & 16) >> 1); // B: n row
    const int lckB  = (lane >> 3) & 1;                 // B: k-half

    float acc[2][8][4];
#pragma unroll
    for (int i = 0; i < 2; i++)
#pragma unroll
        for (int j = 0; j < 8; j++)
#pragma unroll
            for (int q = 0; q < 4; q++) acc[i][j][q] = 0.0f;

    const int NC = K >> 6;

#define ISSUE(i) do { \
        const uint32_t st_ = smb + ((i) % 3) * STAGE_BYTES; \
        const int kt_ = (i) * 64; \
        _Pragma("unroll") \
        for (int t = 0; t < 16; t++) { \
            const int tl  = t >> 2; \
            const int row = (t & 3) * 32 + ldRow; \
            const __nv_bfloat16* src = \
                (tl == 0 ? p0 : tl == 1 ? p1 : tl == 2 ? p2 : p3) \
                + (size_t)row * K + kt_ + ldChk * 8; \
            const uint32_t dst = st_ + tl * 16384u + row * 128u \
                + (uint32_t)((ldChk ^ (row & 7)) << 4); \
            CP_ASYNC16(dst, src); \
        } \
        CP_COMMIT(); \
    } while (0)

    ISSUE(0);
    ISSUE(1);

    for (int i = 0; i < NC; i++) {
        if (i < NC - 1) asm volatile("cp.async.wait_group 1;" ::: "memory");
        else            asm volatile("cp.async.wait_group 0;" ::: "memory");
        __syncthreads();
        if (i + 2 < NC) ISSUE(i + 2);

        const uint32_t st  = smb + (i % 3) * STAGE_BYTES;
        const uint32_t stAh = st;
        const uint32_t stAl = st + 16384;
        const uint32_t stBh = st + 32768;
        const uint32_t stBl = st + 49152;

#pragma unroll
        for (int ks = 0; ks < 4; ks++) {
            uint32_t ah[2][4], al[2][4], bh[4][4], bl[4][4];
            // addresses
            uint32_t aAddr[2], bAddr[4];
#pragma unroll
            for (int mt = 0; mt < 2; mt++) {
                const int r = wm * 32 + mt * 16 + lrowA;
                const int c = ks * 2 + lckA;
                aAddr[mt] = r * 128u + (uint32_t)(((c ^ (r & 7)) & 7) << 4);
            }
#pragma unroll
            for (int nt = 0; nt < 4; nt++) {
                const int r = wn * 64 + nt * 16 + lrowB;
                const int c = ks * 2 + lckB;
                bAddr[nt] = r * 128u + (uint32_t)(((c ^ (r & 7)) & 7) << 4);
            }
            // pass 1: Ah * Bh
#pragma unroll
            for (int mt = 0; mt < 2; mt++) LDSM4(ah[mt], stAh + aAddr[mt]);
#pragma unroll
            for (int nt = 0; nt < 4; nt++) LDSM4(bh[nt], stBh + bAddr[nt]);
#pragma unroll
            for (int mt = 0; mt < 2; mt++)
#pragma unroll
                for (int n8 = 0; n8 < 8; n8++)
                    MMA16816(acc[mt][n8], ah[mt],
                             bh[n8 >> 1][(n8 & 1) * 2], bh[n8 >> 1][(n8 & 1) * 2 + 1]);
            // pass 2: Al * Bh
#pragma unroll
            for (int mt = 0; mt < 2; mt++) LDSM4(al[mt], stAl + aAddr[mt]);
#pragma unroll
            for (int mt = 0; mt < 2; mt++)
#pragma unroll
                for (int n8 = 0; n8 < 8; n8++)
                    MMA16816(acc[mt][n8], al[mt],
                             bh[n8 >> 1][(n8 & 1) * 2], bh[n8 >> 1][(n8 & 1) * 2 + 1]);
            // pass 3: Ah * Bl
#pragma unroll
            for (int nt = 0; nt < 4; nt++) LDSM4(bl[nt], stBl + bAddr[nt]);
#pragma unroll
            for (int mt = 0; mt < 2; mt++)
#pragma unroll
                for (int n8 = 0; n8 < 8; n8++)
                    MMA16816(acc[mt][n8], ah[mt],
                             bl[n8 >> 1][(n8 & 1) * 2], bl[n8 >> 1][(n8 & 1) * 2 + 1]);
        }
        __syncthreads();
    }

    // ---- epilogue: registers -> gmem ----
    const int qrow = lane >> 2;
    const int qcol = (lane & 3) * 2;
#pragma unroll
    for (int mt = 0; mt < 2; mt++) {
#pragma unroll
        for (int h = 0; h < 2; h++) {
            const int row = bm + wm * 32 + mt * 16 + qrow + h * 8;
#pragma unroll
            for (int n8 = 0; n8 < 8; n8++) {
                const int col = bn + wn * 64 + n8 * 8 + qcol;
                float v0 = acc[mt][n8][h * 2 + 0] + bias[col];
                float v1 = acc[mt][n8][h * 2 + 1] + bias[col + 1];
                if (EPI == 0) {
                    v0 = gelu_exact(v0);
                    v1 = gelu_exact(v1);
                    __nv_bfloat16 h2[2], l2[2];
                    split_bf16(v0, h2[0], l2[0]);
                    split_bf16(v1, h2[1], l2[1]);
                    *(uint32_t*)(Chi + (size_t)row * N + col) = *(uint32_t*)h2;
                    *(uint32_t*)(Clo + (size_t)row * N + col) = *(uint32_t*)l2;
                } else {
                    if (EPI == 1) { v0 = gelu_exact(v0); v1 = gelu_exact(v1); }
                    float2 o = make_float2(v0, v1);
                    *(float2*)(Cf + (size_t)row * N + col) = o;
                }
            }
        }
    }
#undef ISSUE
}

// ---------------------------------------------------------------------------
// Prep kernels
// ---------------------------------------------------------------------------
__global__ void split_kernel(const float* __restrict__ in,
                             __nv_bfloat16* __restrict__ hi,
                             __nv_bfloat16* __restrict__ lo, int n4)
{
    const int i = blockIdx.x * 256 + threadIdx.x;
    if (i >= n4) return;
    float4 v = ((const float4*)in)[i];
    __nv_bfloat16 h[4], l[4];
    split_bf16(v.x, h[0], l[0]); split_bf16(v.y, h[1], l[1]);
    split_bf16(v.z, h[2], l[2]); split_bf16(v.w, h[3], l[3]);
    ((uint2*)hi)[i] = *(uint2*)h;
    ((uint2*)lo)[i] = *(uint2*)l;
}

__global__ void wtr_kernel(const float* __restrict__ w, int K, int N,
                           __nv_bfloat16* __restrict__ th,
                           __nv_bfloat16* __restrict__ tl)
{
    const int i = blockIdx.x * 256 + threadIdx.x;
    if (i >= N * K) return;
    const int n = i / K, k = i - n * K;
    __nv_bfloat16 h, l;
    split_bf16(w[(size_t)k * N + n], h, l);
    th[i] = h; tl[i] = l;
}

// forward shift of xh (C=1024, groups of 114); one token per block.
__global__ void shiftf_kernel(const __nv_bfloat16* __restrict__ hi,
                              const __nv_bfloat16* __restrict__ lo,
                              __nv_bfloat16* __restrict__ ohi,
                              __nv_bfloat16* __restrict__ olo)
{
    const int m = blockIdx.x;
    const int y = (m / Wd) % Wd;
    const int x = m % Wd;
    const int c0 = threadIdx.x * 4;
#pragma unroll
    for (int j = 0; j < 4; j++) {
        const int c = c0 + j;
        const int g = c / 114;
        const int sh = c_sh[g], sw = c_sw[g];
        const int ys = y - sh, xs = x - sw;
        __nv_bfloat16 vh = __float2bfloat16(0.0f), vl = vh;
        if ((unsigned)ys < 56u && (unsigned)xs < 56u) {
            const size_t src = (size_t)(m - sh * Wd - sw) * HIDN + c;
            vh = hi[src]; vl = lo[src];
        }
        ohi[(size_t)m * HIDN + c] = vh;
        olo[(size_t)m * HIDN + c] = vl;
    }
}

// combine: comb = inv_shift(hpre)*a0 + wbuf*a1, split to bf16 (C=512, groups 57)
__global__ void combine_kernel(const float* __restrict__ hpre,
                               const float* __restrict__ wbuf,
                               const float* __restrict__ a01,
                               __nv_bfloat16* __restrict__ ohi,
                               __nv_bfloat16* __restrict__ olo)
{
    const int m = blockIdx.x;
    const int b = m / TPB;
    const int y = (m / Wd) % Wd;
    const int x = m % Wd;
    const int c0 = threadIdx.x * 2;
#pragma unroll
    for (int j = 0; j < 2; j++) {
        const int c = c0 + j;
        const int g = c / 57;
        const int sh = c_sh[g], sw = c_sw[g];
        const int ys = y + sh, xs = x + sw;
        float hv = 0.0f;
        if ((unsigned)ys < 56u && (unsigned)xs < 56u)
            hv = hpre[(size_t)(m + sh * Wd + sw) * CIN + c];
        const float wv = wbuf[(size_t)m * CIN + c];
        const float a0 = a01[b * CIN + c];
        const float a1 = a01[2 * CIN + b * CIN + c];
        const float v = hv * a0 + wv * a1;
        __nv_bfloat16 h, l;
        split_bf16(v, h, l);
        ohi[(size_t)m * CIN + c] = h;
        olo[(size_t)m * CIN + c] = l;
    }
}

// ---------------------------------------------------------------------------
// reduce + head (correctness-proven in round 1)
// ---------------------------------------------------------------------------
__global__ void reduce_kernel(const float* __restrict__ hpre,
                              const float* __restrict__ wbuf,
                              float* __restrict__ part)
{
    const int c = threadIdx.x;
    const int b = blockIdx.y;
    const int chunk = blockIdx.x;
    const int g = c / 57;
    const int sh = c_sh[g], sw = c_sw[g];
    float acc = 0.0f;
    const int m0 = b * TPB + chunk * 512;
    for (int it = 0; it < 512; it++) {
        const int m = m0 + it;
        const int y = (m / Wd) % Wd;
        const int x = m % Wd;
        const int ys = y + sh, xs = x + sw;
        float hv = 0.0f;
        if ((unsigned)ys < 56u && (unsigned)xs < 56u)
            hv = hpre[(size_t)(m + sh * Wd + sw) * CIN + c];
        acc += hv + wbuf[(size_t)m * CIN + c];
    }
    part[(size_t)(b * RED_CHUNKS + chunk) * CIN + c] = acc;
}

__global__ void head_kernel(const float* __restrict__ part,
                            const float* __restrict__ rw1_w,
                            const float* __restrict__ rw1_b,
                            const float* __restrict__ rw2_w,
                            const float* __restrict__ rw2_b,
                            float* __restrict__ a01)
{
    __shared__ float s_in[512];
    __shared__ float s_t1[128];
    __shared__ float s_t2[1024];
    const int tid = threadIdx.x;
    for (int b = 0; b < 2; b++) {
        float s = 0.0f;
        for (int p = 0; p < RED_CHUNKS; p++)
            s += part[(size_t)(b * RED_CHUNKS + p) * CIN + tid];
        s_in[tid] = s * (1.0f / (float)TPB);
        __syncthreads();
        if (tid < 128) {
            float acc = rw1_b[tid];
            for (int c = 0; c < 512; c++)
                acc = fmaf(s_in[c], rw1_w[c * 128 + tid], acc);
            s_t1[tid] = gelu_exact(acc);
        }
        __syncthreads();
        for (int n = tid; n < 1024; n += 512) {
            float acc = rw2_b[n];
            for (int j = 0; j < 128; j++)
                acc = fmaf(s_t1[j], rw2_w[j * 1024 + n], acc);
            s_t2[n] = acc;
        }
        __syncthreads();
        {
            const float v0 = s_t2[2 * tid];
            const float v1 = s_t2[2 * tid + 1];
            const float mx = fmaxf(v0, v1);
            const float e0 = expf(v0 - mx);
            const float e1 = expf(v1 - mx);
            const float inv = 1.0f / (e0 + e1);
            a01[b * CIN + tid]           = e0 * inv;
            a01[2 * CIN + b * CIN + tid] = e1 * inv;
        }
        __syncthreads();
    }
}

// ---------------------------------------------------------------------------
extern "C" void kernel_launch(void* const* d_in, const int* in_sizes, int n_in,
                              void* d_out, int out_size)
{
    const float* x      = (const float*)d_in[0];
    const float* fc_w   = (const float*)d_in[1];
    const float* fc_b   = (const float*)d_in[2];
    const float* fc1_w  = (const float*)d_in[3];
    const float* fc1_b  = (const float*)d_in[4];
    const float* fc2_w  = (const float*)d_in[5];
    const float* fc2_b  = (const float*)d_in[6];
    const float* rw1_w  = (const float*)d_in[7];
    const float* rw1_b  = (const float*)d_in[8];
    const float* rw2_w  = (const float*)d_in[9];
    const float* rw2_b  = (const float*)d_in[10];
    const float* proj_w = (const float*)d_in[11];
    const float* proj_b = (const float*)d_in[12];
    float* out = (float*)d_out;

    __nv_bfloat16 *xhi, *xlo, *xhhi, *xhlo, *xshi, *xslo, *cmhi, *cmlo;
    __nv_bfloat16 *w1hi, *w1lo, *w2hi, *w2lo, *w3hi, *w3lo, *w4hi, *w4lo;
    float *hpre, *wbuf, *part, *a01;
    cudaGetSymbolAddress((void**)&xhi,  g_xhi);  cudaGetSymbolAddress((void**)&xlo,  g_xlo);
    cudaGetSymbolAddress((void**)&xhhi, g_xhhi); cudaGetSymbolAddress((void**)&xhlo, g_xhlo);
    cudaGetSymbolAddress((void**)&xshi, g_xshi); cudaGetSymbolAddress((void**)&xslo, g_xslo);
    cudaGetSymbolAddress((void**)&cmhi, g_cmhi); cudaGetSymbolAddress((void**)&cmlo, g_cmlo);
    cudaGetSymbolAddress((void**)&w1hi, g_w1hi); cudaGetSymbolAddress((void**)&w1lo, g_w1lo);
    cudaGetSymbolAddress((void**)&w2hi, g_w2hi); cudaGetSymbolAddress((void**)&w2lo, g_w2lo);
    cudaGetSymbolAddress((void**)&w3hi, g_w3hi); cudaGetSymbolAddress((void**)&w3lo, g_w3lo);
    cudaGetSymbolAddress((void**)&w4hi, g_w4hi); cudaGetSymbolAddress((void**)&w4lo, g_w4lo);
    cudaGetSymbolAddress((void**)&hpre, g_hpre); cudaGetSymbolAddress((void**)&wbuf, g_wbuf);
    cudaGetSymbolAddress((void**)&part, g_part); cudaGetSymbolAddress((void**)&a01,  g_a01);

    cudaFuncSetAttribute(mma_gemm<0>, cudaFuncAttributeMaxDynamicSharedMemorySize, GEMM_SMEM);
    cudaFuncSetAttribute(mma_gemm<1>, cudaFuncAttributeMaxDynamicSharedMemorySize, GEMM_SMEM);
    cudaFuncSetAttribute(mma_gemm<2>, cudaFuncAttributeMaxDynamicSharedMemorySize, GEMM_SMEM);

    // weights: transpose + split to bf16 hi/lo
    wtr_kernel<<<(HIDN * CIN + 255) / 256, 256>>>(fc_w,  CIN,  HIDN, w1hi, w1lo);
    wtr_kernel<<<(CIN * HIDN + 255) / 256, 256>>>(fc1_w, HIDN, CIN,  w2hi, w2lo);
    wtr_kernel<<<(CIN * HIDN + 255) / 256, 256>>>(fc2_w, HIDN, CIN,  w3hi, w3lo);
    wtr_kernel<<<(CIN * CIN  + 255) / 256, 256>>>(proj_w, CIN, CIN,  w4hi, w4lo);

    // x -> bf16 hi/lo
    split_kernel<<<(NTOK * CIN / 4 + 255) / 256, 256>>>(x, xhi, xlo, NTOK * CIN / 4);

    // 1) xh = gelu(x @ fc_w + b) -> bf16 hi/lo   [50176,1024]
    mma_gemm<0><<<dim3(HIDN / 128, NTOK / 128), 256, GEMM_SMEM>>>(
        xhi, xlo, w1hi, w1lo, fc_b, HIDN, CIN, nullptr, xhhi, xhlo);

    // forward shift of xh
    shiftf_kernel<<<NTOK, 256>>>(xhhi, xhlo, xshi, xslo);

    // 2) hpre = gelu(shift(xh) @ fc1_w + b) -> f32
    mma_gemm<1><<<dim3(CIN / 128, NTOK / 128), 256, GEMM_SMEM>>>(
        xshi, xslo, w2hi, w2lo, fc1_b, CIN, HIDN, hpre, nullptr, nullptr);

    // 3) wbuf = gelu(xh @ fc2_w + b) -> f32
    mma_gemm<1><<<dim3(CIN / 128, NTOK / 128), 256, GEMM_SMEM>>>(
        xhhi, xhlo, w3hi, w3lo, fc2_b, CIN, HIDN, wbuf, nullptr, nullptr);

    // 4) mean over tokens + head MLP + pairwise softmax
    reduce_kernel<<<dim3(RED_CHUNKS, 2), 512>>>(hpre, wbuf, part);
    head_kernel<<<1, 512>>>(part, rw1_w, rw1_b, rw2_w, rw2_b, a01);

    // 5) comb = h*a0 + w*a1 -> bf16 hi/lo
    combine_kernel<<<NTOK, 256>>>(hpre, wbuf, a01, cmhi, cmlo);

    // 6) out = comb @ proj_w + proj_b -> f32
    mma_gemm<2><<<dim3(CIN / 128, NTOK / 128), 256, GEMM_SMEM>>>(
        cmhi, cmlo, w4hi, w4lo, proj_b, CIN, CIN, out, nullptr, nullptr);
}

// round 10
// speedup vs baseline: 3.6676x; 1.2673x over previous
#include <cuda_runtime.h>
#include <cuda_fp16.h>
#include <math.h>
#include <cstdint>

// ---------------------------------------------------------------------------
// Shapes: B=2, T=8, H=W=56, C=512, HID=1024. NTOK = 50176.
// ---------------------------------------------------------------------------
#define NTOK 50176
#define TPB  25088
#define Wd   56
#define CIN  512
#define HIDN 1024
#define RED_CHUNKS 49

// ---------------------------------------------------------------------------
// Scratch (__device__ globals; allocation-free rule). 128B aligned for cp.async.
// A-side operands: fp16 hi/lo split. B-side (weights): single fp16.
// ---------------------------------------------------------------------------
__device__ __align__(128) __half g_xhi [(size_t)NTOK * CIN];
__device__ __align__(128) __half g_xlo [(size_t)NTOK * CIN];
__device__ __align__(128) __half g_xhhi[(size_t)NTOK * HIDN];
__device__ __align__(128) __half g_xhlo[(size_t)NTOK * HIDN];
__device__ __align__(128) __half g_xshi[(size_t)NTOK * HIDN];
__device__ __align__(128) __half g_xslo[(size_t)NTOK * HIDN];
__device__ __align__(128) float  g_hpre[(size_t)NTOK * CIN];
__device__ __align__(128) float  g_wbuf[(size_t)NTOK * CIN];
__device__ __align__(128) __half g_cmhi[(size_t)NTOK * CIN];
__device__ __align__(128) __half g_cmlo[(size_t)NTOK * CIN];
__device__ __align__(128) __half g_w1[HIDN * CIN];   // fc_w^T
__device__ __align__(128) __half g_w2[CIN * HIDN];   // fc1_w^T
__device__ __align__(128) __half g_w3[CIN * HIDN];   // fc2_w^T
__device__ __align__(128) __half g_w4[CIN * CIN];    // proj_w^T
__device__ float g_part[2 * RED_CHUNKS * CIN];
__device__ float g_a01 [4 * CIN];

__constant__ int c_sh[9] = { 1, 1, 1, 0, 0, 0,-1,-1,-1};
__constant__ int c_sw[9] = { 1, 0,-1, 1, 0,-1, 1, 0,-1};

__device__ __forceinline__ float gelu_exact(float v) {
    return 0.5f * v * (1.0f + erff(v * 0.70710678118654752f));
}
__device__ __forceinline__ void split_f16(float v, __half& h, __half& l) {
    h = __float2half_rn(v);
    l = __float2half_rn(v - __half2float(h));
}
__device__ __forceinline__ uint32_t smem_u32(const void* p) {
    uint32_t a;
    asm("{ .reg .u64 t; cvta.to.shared.u64 t, %1; cvt.u32.u64 %0, t; }" : "=r"(a) : "l"(p));
    return a;
}

#define CP_ASYNC16(dst, src) \
    asm volatile("cp.async.cg.shared.global [%0], [%1], 16;" :: "r"(dst), "l"(src) : "memory")
#define CP_COMMIT() asm volatile("cp.async.commit_group;" ::: "memory")

#define LDSM4(r, a) \
    asm volatile("ldmatrix.sync.aligned.m8n8.x4.shared.b16 {%0,%1,%2,%3}, [%4];" \
        : "=r"((r)[0]), "=r"((r)[1]), "=r"((r)[2]), "=r"((r)[3]) : "r"(a))

#define MMA16816(d, a, b0, b1) \
    asm volatile("mma.sync.aligned.m16n8k16.row.col.f32.f16.f16.f32 " \
        "{%0,%1,%2,%3}, {%4,%5,%6,%7}, {%8,%9}, {%0,%1,%2,%3};" \
        : "+f"((d)[0]), "+f"((d)[1]), "+f"((d)[2]), "+f"((d)[3]) \
        : "r"((a)[0]), "r"((a)[1]), "r"((a)[2]), "r"((a)[3]), "r"(b0), "r"(b1))

// ---------------------------------------------------------------------------
// HMMA GEMM: C[M,N] = epi(A@W + bias), A = Ahi+Alo [M,K] fp16, W^T = B [N,K] fp16.
// result = Ah*B + Al*B (2 passes; only error = B fp16 quantization ~1.4e-4).
// CTA 128x128, warp grid 4(m) x 2(n), warp tile 32x64, K-chunk 64, 4 stages.
// EPI 0: gelu -> split fp16.  EPI 1: gelu -> f32.  EPI 2: bias only -> f32.
// ---------------------------------------------------------------------------
#define STAGE_BYTES 49152
#define GEMM_SMEM   (4 * STAGE_BYTES)

template <int EPI>
__global__ __launch_bounds__(256, 1)
void mma_gemm(const __half* __restrict__ Ahi, const __half* __restrict__ Alo,
              const __half* __restrict__ Bw,
              const float* __restrict__ bias, int N, int K,
              float* __restrict__ Cf, __half* __restrict__ Chi,
              __half* __restrict__ Clo)
{
    extern __shared__ char smraw[];
    const uint32_t smb = smem_u32(smraw);

    const int tid  = threadIdx.x;
    const int wid  = tid >> 5;
    const int lane = tid & 31;
    const int wm   = wid & 3;        // m offset wm*32
    const int wn   = wid >> 2;       // n offset wn*64
    const int bm   = blockIdx.y * 128;
    const int bn   = blockIdx.x * 128;

    const __half* p0 = Ahi + (size_t)bm * K;
    const __half* p1 = Alo + (size_t)bm * K;
    const __half* p2 = Bw  + (size_t)bn * K;

    const int ldRow = tid >> 3;          // 0..31 (+32*(t&3))
    const int ldChk = tid & 7;

    const int lrowA = lane & 15;
    const int lckA  = lane >> 4;
    const int lrowB = (lane & 7) + ((lane & 16) >> 1);
    const int lckB  = (lane >> 3) & 1;

    float acc[2][8][4];
#pragma unroll
    for (int i = 0; i < 2; i++)
#pragma unroll
        for (int j = 0; j < 8; j++)
#pragma unroll
            for (int q = 0; q < 4; q++) acc[i][j][q] = 0.0f;

    const int NC = K >> 6;

#define ISSUE(i) do { \
        const uint32_t st_ = smb + ((i) & 3) * STAGE_BYTES; \
        const int kt_ = (i) * 64; \
        _Pragma("unroll") \
        for (int t = 0; t < 12; t++) { \
            const int tl  = t >> 2; \
            const int row = (t & 3) * 32 + ldRow; \
            const __half* src = \
                (tl == 0 ? p0 : tl == 1 ? p1 : p2) \
                + (size_t)row * K + kt_ + ldChk * 8; \
            const uint32_t dst = st_ + tl * 16384u + row * 128u \
                + (uint32_t)((ldChk ^ (row & 7)) << 4); \
            CP_ASYNC16(dst, src); \
        } \
        CP_COMMIT(); \
    } while (0)

    ISSUE(0);
    ISSUE(1);
    ISSUE(2);

    for (int i = 0; i < NC; i++) {
        // In-flight groups at this point: chunks i .. min(i+2, NC-1).
        // To guarantee group i landed, allow only (in_flight - 1) pending.
        const int rem = NC - 1 - i;
        if (rem >= 2)      asm volatile("cp.async.wait_group 2;" ::: "memory");
        else if (rem == 1) asm volatile("cp.async.wait_group 1;" ::: "memory");
        else               asm volatile("cp.async.wait_group 0;" ::: "memory");
        __syncthreads();
        if (i + 3 < NC) ISSUE(i + 3);

        const uint32_t st   = smb + (i & 3) * STAGE_BYTES;
        const uint32_t stAh = st;
        const uint32_t stAl = st + 16384;
        const uint32_t stB  = st + 32768;

#pragma unroll
        for (int ks = 0; ks < 4; ks++) {
            uint32_t ah[2][4], al[2][4], bw[4][4];
            uint32_t aAddr[2], bAddr[4];
#pragma unroll
            for (int mt = 0; mt < 2; mt++) {
                const int r = wm * 32 + mt * 16 + lrowA;
                const int c = ks * 2 + lckA;
                aAddr[mt] = r * 128u + (uint32_t)(((c ^ (r & 7)) & 7) << 4);
            }
#pragma unroll
            for (int nt = 0; nt < 4; nt++) {
                const int r = wn * 64 + nt * 16 + lrowB;
                const int c = ks * 2 + lckB;
                bAddr[nt] = r * 128u + (uint32_t)(((c ^ (r & 7)) & 7) << 4);
            }
#pragma unroll
            for (int nt = 0; nt < 4; nt++) LDSM4(bw[nt], stB + bAddr[nt]);
            // pass 1: Ah * B
#pragma unroll
            for (int mt = 0; mt < 2; mt++) LDSM4(ah[mt], stAh + aAddr[mt]);
#pragma unroll
            for (int mt = 0; mt < 2; mt++)
#pragma unroll
                for (int n8 = 0; n8 < 8; n8++)
                    MMA16816(acc[mt][n8], ah[mt],
                             bw[n8 >> 1][(n8 & 1) * 2], bw[n8 >> 1][(n8 & 1) * 2 + 1]);
            // pass 2: Al * B
#pragma unroll
            for (int mt = 0; mt < 2; mt++) LDSM4(al[mt], stAl + aAddr[mt]);
#pragma unroll
            for (int mt = 0; mt < 2; mt++)
#pragma unroll
                for (int n8 = 0; n8 < 8; n8++)
                    MMA16816(acc[mt][n8], al[mt],
                             bw[n8 >> 1][(n8 & 1) * 2], bw[n8 >> 1][(n8 & 1) * 2 + 1]);
        }
        __syncthreads();
    }

    // ---- epilogue: registers -> gmem ----
    const int qrow = lane >> 2;
    const int qcol = (lane & 3) * 2;
#pragma unroll
    for (int mt = 0; mt < 2; mt++) {
#pragma unroll
        for (int h = 0; h < 2; h++) {
            const int row = bm + wm * 32 + mt * 16 + qrow + h * 8;
#pragma unroll
            for (int n8 = 0; n8 < 8; n8++) {
                const int col = bn + wn * 64 + n8 * 8 + qcol;
                float v0 = acc[mt][n8][h * 2 + 0] + bias[col];
                float v1 = acc[mt][n8][h * 2 + 1] + bias[col + 1];
                if (EPI == 0) {
                    v0 = gelu_exact(v0);
                    v1 = gelu_exact(v1);
                    __half h2[2], l2[2];
                    split_f16(v0, h2[0], l2[0]);
                    split_f16(v1, h2[1], l2[1]);
                    *(uint32_t*)(Chi + (size_t)row * N + col) = *(uint32_t*)h2;
                    *(uint32_t*)(Clo + (size_t)row * N + col) = *(uint32_t*)l2;
                } else {
                    if (EPI == 1) { v0 = gelu_exact(v0); v1 = gelu_exact(v1); }
                    float2 o = make_float2(v0, v1);
                    *(float2*)(Cf + (size_t)row * N + col) = o;
                }
            }
        }
    }
#undef ISSUE
}

// ---------------------------------------------------------------------------
// Prep kernels
// ---------------------------------------------------------------------------
__global__ void split_kernel(const float* __restrict__ in,
                             __half* __restrict__ hi,
                             __half* __restrict__ lo, int n4)
{
    const int i = blockIdx.x * 256 + threadIdx.x;
    if (i >= n4) return;
    float4 v = ((const float4*)in)[i];
    __half h[4], l[4];
    split_f16(v.x, h[0], l[0]); split_f16(v.y, h[1], l[1]);
    split_f16(v.z, h[2], l[2]); split_f16(v.w, h[3], l[3]);
    ((uint2*)hi)[i] = *(uint2*)h;
    ((uint2*)lo)[i] = *(uint2*)l;
}

__global__ void wtr_kernel(const float* __restrict__ w, int K, int N,
                           __half* __restrict__ t)
{
    const int i = blockIdx.x * 256 + threadIdx.x;
    if (i >= N * K) return;
    const int n = i / K, k = i - n * K;
    t[i] = __float2half_rn(w[(size_t)k * N + n]);
}

// forward shift of xh (C=1024, groups of 114); one token per block.
__global__ void shiftf_kernel(const __half* __restrict__ hi,
                              const __half* __restrict__ lo,
                              __half* __restrict__ ohi,
                              __half* __restrict__ olo)
{
    const int m = blockIdx.x;
    const int y = (m / Wd) % Wd;
    const int x = m % Wd;
    const int c0 = threadIdx.x * 4;
#pragma unroll
    for (int j = 0; j < 4; j++) {
        const int c = c0 + j;
        const int g = c / 114;
        const int sh = c_sh[g], sw = c_sw[g];
        const int ys = y - sh, xs = x - sw;
        __half vh = __float2half_rn(0.0f), vl = vh;
        if ((unsigned)ys < 56u && (unsigned)xs < 56u) {
            const size_t src = (size_t)(m - sh * Wd - sw) * HIDN + c;
            vh = hi[src]; vl = lo[src];
        }
        ohi[(size_t)m * HIDN + c] = vh;
        olo[(size_t)m * HIDN + c] = vl;
    }
}

// combine: comb = inv_shift(hpre)*a0 + wbuf*a1, split to fp16 (C=512, groups 57)
__global__ void combine_kernel(const float* __restrict__ hpre,
                               const float* __restrict__ wbuf,
                               const float* __restrict__ a01,
                               __half* __restrict__ ohi,
                               __half* __restrict__ olo)
{
    const int m = blockIdx.x;
    const int b = m / TPB;
    const int y = (m / Wd) % Wd;
    const int x = m % Wd;
    const int c0 = threadIdx.x * 2;
#pragma unroll
    for (int j = 0; j < 2; j++) {
        const int c = c0 + j;
        const int g = c / 57;
        const int sh = c_sh[g], sw = c_sw[g];
        const int ys = y + sh, xs = x + sw;
        float hv = 0.0f;
        if ((unsigned)ys < 56u && (unsigned)xs < 56u)
            hv = hpre[(size_t)(m + sh * Wd + sw) * CIN + c];
        const float wv = wbuf[(size_t)m * CIN + c];
        const float a0 = a01[b * CIN + c];
        const float a1 = a01[2 * CIN + b * CIN + c];
        const float v = hv * a0 + wv * a1;
        __half h, l;
        split_f16(v, h, l);
        ohi[(size_t)m * CIN + c] = h;
        olo[(size_t)m * CIN + c] = l;
    }
}

// ---------------------------------------------------------------------------
// reduce + head (correctness-proven)
// ---------------------------------------------------------------------------
__global__ void reduce_kernel(const float* __restrict__ hpre,
                              const float* __restrict__ wbuf,
                              float* __restrict__ part)
{
    const int c = threadIdx.x;
    const int b = blockIdx.y;
    const int chunk = blockIdx.x;
    const int g = c / 57;
    const int sh = c_sh[g], sw = c_sw[g];
    float acc = 0.0f;
    const int m0 = b * TPB + chunk * 512;
    for (int it = 0; it < 512; it++) {
        const int m = m0 + it;
        const int y = (m / Wd) % Wd;
        const int x = m % Wd;
        const int ys = y + sh, xs = x + sw;
        float hv = 0.0f;
        if ((unsigned)ys < 56u && (unsigned)xs < 56u)
            hv = hpre[(size_t)(m + sh * Wd + sw) * CIN + c];
        acc += hv + wbuf[(size_t)m * CIN + c];
    }
    part[(size_t)(b * RED_CHUNKS + chunk) * CIN + c] = acc;
}

__global__ void head_kernel(const float* __restrict__ part,
                            const float* __restrict__ rw1_w,
                            const float* __restrict__ rw1_b,
                            const float* __restrict__ rw2_w,
                            const float* __restrict__ rw2_b,
                            float* __restrict__ a01)
{
    __shared__ float s_in[512];
    __shared__ float s_t1[128];
    __shared__ float s_t2[1024];
    const int tid = threadIdx.x;
    for (int b = 0; b < 2; b++) {
        float s = 0.0f;
        for (int p = 0; p < RED_CHUNKS; p++)
            s += part[(size_t)(b * RED_CHUNKS + p) * CIN + tid];
        s_in[tid] = s * (1.0f / (float)TPB);
        __syncthreads();
        if (tid < 128) {
            float acc = rw1_b[tid];
            for (int c = 0; c < 512; c++)
                acc = fmaf(s_in[c], rw1_w[c * 128 + tid], acc);
            s_t1[tid] = gelu_exact(acc);
        }
        __syncthreads();
        for (int n = tid; n < 1024; n += 512) {
            float acc = rw2_b[n];
            for (int j = 0; j < 128; j++)
                acc = fmaf(s_t1[j], rw2_w[j * 1024 + n], acc);
            s_t2[n] = acc;
        }
        __syncthreads();
        {
            const float v0 = s_t2[2 * tid];
            const float v1 = s_t2[2 * tid + 1];
            const float mx = fmaxf(v0, v1);
            const float e0 = expf(v0 - mx);
            const float e1 = expf(v1 - mx);
            const float inv = 1.0f / (e0 + e1);
            a01[b * CIN + tid]           = e0 * inv;
            a01[2 * CIN + b * CIN + tid] = e1 * inv;
        }
        __syncthreads();
    }
}

// ---------------------------------------------------------------------------
extern "C" void kernel_launch(void* const* d_in, const int* in_sizes, int n_in,
                              void* d_out, int out_size)
{
    const float* x      = (const float*)d_in[0];
    const float* fc_w   = (const float*)d_in[1];
    const float* fc_b   = (const float*)d_in[2];
    const float* fc1_w  = (const float*)d_in[3];
    const float* fc1_b  = (const float*)d_in[4];
    const float* fc2_w  = (const float*)d_in[5];
    const float* fc2_b  = (const float*)d_in[6];
    const float* rw1_w  = (const float*)d_in[7];
    const float* rw1_b  = (const float*)d_in[8];
    const float* rw2_w  = (const float*)d_in[9];
    const float* rw2_b  = (const float*)d_in[10];
    const float* proj_w = (const float*)d_in[11];
    const float* proj_b = (const float*)d_in[12];
    float* out = (float*)d_out;

    __half *xhi, *xlo, *xhhi, *xhlo, *xshi, *xslo, *cmhi, *cmlo;
    __half *w1, *w2, *w3, *w4;
    float *hpre, *wbuf, *part, *a01;
    cudaGetSymbolAddress((void**)&xhi,  g_xhi);  cudaGetSymbolAddress((void**)&xlo,  g_xlo);
    cudaGetSymbolAddress((void**)&xhhi, g_xhhi); cudaGetSymbolAddress((void**)&xhlo, g_xhlo);
    cudaGetSymbolAddress((void**)&xshi, g_xshi); cudaGetSymbolAddress((void**)&xslo, g_xslo);
    cudaGetSymbolAddress((void**)&cmhi, g_cmhi); cudaGetSymbolAddress((void**)&cmlo, g_cmlo);
    cudaGetSymbolAddress((void**)&w1, g_w1); cudaGetSymbolAddress((void**)&w2, g_w2);
    cudaGetSymbolAddress((void**)&w3, g_w3); cudaGetSymbolAddress((void**)&w4, g_w4);
    cudaGetSymbolAddress((void**)&hpre, g_hpre); cudaGetSymbolAddress((void**)&wbuf, g_wbuf);
    cudaGetSymbolAddress((void**)&part, g_part); cudaGetSymbolAddress((void**)&a01,  g_a01);

    cudaFuncSetAttribute(mma_gemm<0>, cudaFuncAttributeMaxDynamicSharedMemorySize, GEMM_SMEM);
    cudaFuncSetAttribute(mma_gemm<1>, cudaFuncAttributeMaxDynamicSharedMemorySize, GEMM_SMEM);
    cudaFuncSetAttribute(mma_gemm<2>, cudaFuncAttributeMaxDynamicSharedMemorySize, GEMM_SMEM);

    // weights: transpose -> fp16 [N][K]
    wtr_kernel<<<(HIDN * CIN + 255) / 256, 256>>>(fc_w,  CIN,  HIDN, w1);
    wtr_kernel<<<(CIN * HIDN + 255) / 256, 256>>>(fc1_w, HIDN, CIN,  w2);
    wtr_kernel<<<(CIN * HIDN + 255) / 256, 256>>>(fc2_w, HIDN, CIN,  w3);
    wtr_kernel<<<(CIN * CIN  + 255) / 256, 256>>>(proj_w, CIN, CIN,  w4);

    // x -> fp16 hi/lo
    split_kernel<<<(NTOK * CIN / 4 + 255) / 256, 256>>>(x, xhi, xlo, NTOK * CIN / 4);

    // 1) xh = gelu(x @ fc_w + b) -> fp16 hi/lo   [50176,1024]
    mma_gemm<0><<<dim3(HIDN / 128, NTOK / 128), 256, GEMM_SMEM>>>(
        xhi, xlo, w1, fc_b, HIDN, CIN, nullptr, xhhi, xhlo);

    // forward shift of xh
    shiftf_kernel<<<NTOK, 256>>>(xhhi, xhlo, xshi, xslo);

    // 2) hpre = gelu(shift(xh) @ fc1_w + b) -> f32
    mma_gemm<1><<<dim3(CIN / 128, NTOK / 128), 256, GEMM_SMEM>>>(
        xshi, xslo, w2, fc1_b, CIN, HIDN, hpre, nullptr, nullptr);

    // 3) wbuf = gelu(xh @ fc2_w + b) -> f32
    mma_gemm<1><<<dim3(CIN / 128, NTOK / 128), 256, GEMM_SMEM>>>(
        xhhi, xhlo, w3, fc2_b, CIN, HIDN, wbuf, nullptr, nullptr);

    // 4) mean over tokens + head MLP + pairwise softmax
    reduce_kernel<<<dim3(RED_CHUNKS, 2), 512>>>(hpre, wbuf, part);
    head_kernel<<<1, 512>>>(part, rw1_w, rw1_b, rw2_w, rw2_b, a01);

    // 5) comb = h*a0 + w*a1 -> fp16 hi/lo
    combine_kernel<<<NTOK, 256>>>(hpre, wbuf, a01, cmhi, cmlo);

    // 6) out = comb @ proj_w + proj_b -> f32
    mma_gemm<2><<<dim3(CIN / 128, NTOK / 128), 256, GEMM_SMEM>>>(
        cmhi, cmlo, w4, proj_b, CIN, CIN, out, nullptr, nullptr);
}

// round 11
// speedup vs baseline: 4.0227x; 1.0968x over previous
#include <cuda_runtime.h>
#include <cuda_fp16.h>
#include <math.h>
#include <cstdint>

// ---------------------------------------------------------------------------
// Shapes: B=2, T=8, H=W=56, C=512, HID=1024. NTOK = 50176.
// ---------------------------------------------------------------------------
#define NTOK 50176
#define TPB  25088
#define Wd   56
#define CIN  512
#define HIDN 1024
#define RED_CHUNKS 49

// ---------------------------------------------------------------------------
// Scratch (__device__ globals; allocation-free rule). 128B aligned for cp.async.
// ---------------------------------------------------------------------------
__device__ __align__(128) __half g_xhi [(size_t)NTOK * CIN];    // x -> fp16
__device__ __align__(128) __half g_xhhi[(size_t)NTOK * HIDN];   // xh hi
__device__ __align__(128) __half g_xhlo[(size_t)NTOK * HIDN];   // xh lo
__device__ __align__(128) float  g_hpre[(size_t)NTOK * CIN];
__device__ __align__(128) float  g_wbuf[(size_t)NTOK * CIN];
__device__ __align__(128) __half g_cmhi[(size_t)NTOK * CIN];
__device__ __align__(128) __half g_cmlo[(size_t)NTOK * CIN];
__device__ __align__(128) __half g_w1[HIDN * CIN];   // fc_w^T
__device__ __align__(128) __half g_w2[CIN * HIDN];   // fc1_w^T
__device__ __align__(128) __half g_w3[CIN * HIDN];   // fc2_w^T
__device__ __align__(128) __half g_w4[CIN * CIN];    // proj_w^T
__device__ float g_part[2 * RED_CHUNKS * CIN];
__device__ float g_a01 [4 * CIN];

__constant__ int c_sh[9] = { 1, 1, 1, 0, 0, 0,-1,-1,-1};
__constant__ int c_sw[9] = { 1, 0,-1, 1, 0,-1, 1, 0,-1};

__device__ __forceinline__ float gelu_exact(float v) {
    return 0.5f * v * (1.0f + erff(v * 0.70710678118654752f));
}
__device__ __forceinline__ void split_f16(float v, __half& h, __half& l) {
    h = __float2half_rn(v);
    l = __float2half_rn(v - __half2float(h));
}
__device__ __forceinline__ uint32_t smem_u32(const void* p) {
    uint32_t a;
    asm("{ .reg .u64 t; cvta.to.shared.u64 t, %1; cvt.u32.u64 %0, t; }" : "=r"(a) : "l"(p));
    return a;
}

#define CP_ASYNC16(dst, src) \
    asm volatile("cp.async.cg.shared.global [%0], [%1], 16;" :: "r"(dst), "l"(src) : "memory")
// 4-byte cp.async with zero-fill when n==0 (ignore-src form)
#define CP_ASYNC4Z(dst, src, n) \
    asm volatile("cp.async.ca.shared.global [%0], [%1], 4, %2;" :: "r"(dst), "l"(src), "r"(n) : "memory")
#define CP_COMMIT() asm volatile("cp.async.commit_group;" ::: "memory")

#define LDSM4(r, a) \
    asm volatile("ldmatrix.sync.aligned.m8n8.x4.shared.b16 {%0,%1,%2,%3}, [%4];" \
        : "=r"((r)[0]), "=r"((r)[1]), "=r"((r)[2]), "=r"((r)[3]) : "r"(a))

#define MMA16816(d, a, b0, b1) \
    asm volatile("mma.sync.aligned.m16n8k16.row.col.f32.f16.f16.f32 " \
        "{%0,%1,%2,%3}, {%4,%5,%6,%7}, {%8,%9}, {%0,%1,%2,%3};" \
        : "+f"((d)[0]), "+f"((d)[1]), "+f"((d)[2]), "+f"((d)[3]) \
        : "r"((a)[0]), "r"((a)[1]), "r"((a)[2]), "r"((a)[3]), "r"(b0), "r"(b1))

// ---------------------------------------------------------------------------
// HMMA GEMM: C[M,N] = epi(A@W + bias).
//   NPASS=2: A = Ahi+Alo (fp16 split, exact A) -> 2 MMA passes.
//   NPASS=1: A = Ahi only -> 1 MMA pass.
//   SHIFT=1: forward patch-shift fused into A-tile loads via 4B zfill cp.async
//            (K=1024, channel groups of 114; boundaries even => 4B chunks never
//            straddle a group).
// CTA 128x128, warps 4(m)x2(n), warp tile 32x64, K-chunk 64, 4-stage cp.async.
// EPI 0: gelu -> split fp16.  EPI 1: gelu -> f32.  EPI 2: bias only -> f32.
// ---------------------------------------------------------------------------
template <int EPI, int NPASS, int SHIFT>
__global__ __launch_bounds__(256, 1)
void mma_gemm(const __half* __restrict__ Ahi, const __half* __restrict__ Alo,
              const __half* __restrict__ Bw,
              const float* __restrict__ bias, int N, int K,
              float* __restrict__ Cf, __half* __restrict__ Chi,
              __half* __restrict__ Clo)
{
    constexpr uint32_t SB = (NPASS + 1) * 16384u;   // stage stride
    extern __shared__ char smraw[];
    const uint32_t smb = smem_u32(smraw);

    const int tid  = threadIdx.x;
    const int wid  = tid >> 5;
    const int lane = tid & 31;
    const int wm   = wid & 3;
    const int wn   = wid >> 2;
    const int bm   = blockIdx.y * 128;
    const int bn   = blockIdx.x * 128;

    const __half* p0 = Ahi + (size_t)bm * K;
    const __half* p1 = (NPASS == 2) ? (Alo + (size_t)bm * K) : nullptr;
    const __half* p2 = Bw  + (size_t)bn * K;

    const int lrowA = lane & 15;
    const int lckA  = lane >> 4;
    const int lrowB = (lane & 7) + ((lane & 16) >> 1);
    const int lckB  = (lane >> 3) & 1;

    float acc[2][8][4];
#pragma unroll
    for (int i = 0; i < 2; i++)
#pragma unroll
        for (int j = 0; j < 8; j++)
#pragma unroll
            for (int q = 0; q < 4; q++) acc[i][j][q] = 0.0f;

    const int NC = K >> 6;

    auto issue = [&](int ci) {
        const uint32_t st_ = smb + (uint32_t)(ci & 3) * SB;
        const int kt_ = ci * 64;
        if (SHIFT == 0) {
            // all tiles via 16B chunks: NPASS A tiles + 1 B tile
#pragma unroll
            for (int t = 0; t < 4 * (NPASS + 1); t++) {
                const int tl  = t >> 2;
                const int row = (t & 3) * 32 + (tid >> 3);
                const __half* base = (tl == 0) ? p0
                                   : ((NPASS == 2 && tl == 1) ? p1 : p2);
                const __half* src = base + (size_t)row * K + kt_ + (tid & 7) * 8;
                const uint32_t dst = st_ + tl * 16384u + row * 128u
                    + (uint32_t)(((tid & 7) ^ (row & 7)) << 4);
                CP_ASYNC16(dst, src);
            }
        } else {
            // B via 16B at tile slot NPASS
#pragma unroll
            for (int t = 0; t < 4; t++) {
                const int row = t * 32 + (tid >> 3);
                const __half* src = p2 + (size_t)row * K + kt_ + (tid & 7) * 8;
                const uint32_t dst = st_ + NPASS * 16384u + row * 128u
                    + (uint32_t)(((tid & 7) ^ (row & 7)) << 4);
                CP_ASYNC16(dst, src);
            }
            // A hi/lo via 4B zfill with fused forward shift.
            // Thread owns column pair kcol = kt + 2*(tid&31): one group per thread.
            const int cA   = tid & 31;
            const int kcol = kt_ + 2 * cA;
            const int g    = kcol / 114;
            const int sh   = c_sh[g], sw = c_sw[g];
            const int roff = sh * Wd + sw;
            const uint32_t dbase = (uint32_t)((cA & 3) * 4);
#pragma unroll
            for (int t = 0; t < 16; t++) {
                const int row = t * 8 + (tid >> 5);
                const int m = bm + row;
                const int y = (m / Wd) % Wd;
                const int x = m % Wd;
                const int ys = y - sh, xs = x - sw;
                const bool val = ((unsigned)ys < 56u) && ((unsigned)xs < 56u);
                const int srow = val ? (row - roff) : row;
                const int nbytes = val ? 4 : 0;
                const uint32_t dst = st_ + row * 128u
                    + (uint32_t)((((cA >> 2) ^ (row & 7)) << 4)) + dbase;
                CP_ASYNC4Z(dst,          p0 + (size_t)srow * K + kcol, nbytes);
                CP_ASYNC4Z(dst + 16384u, p1 + (size_t)srow * K + kcol, nbytes);
            }
        }
        CP_COMMIT();
    };

    issue(0);
    issue(1);
    issue(2);

    for (int i = 0; i < NC; i++) {
        // In-flight groups: chunks i .. min(i+2, NC-1). Guarantee group i landed.
        const int rem = NC - 1 - i;
        if (rem >= 2)      asm volatile("cp.async.wait_group 2;" ::: "memory");
        else if (rem == 1) asm volatile("cp.async.wait_group 1;" ::: "memory");
        else               asm volatile("cp.async.wait_group 0;" ::: "memory");
        __syncthreads();
        if (i + 3 < NC) issue(i + 3);

        const uint32_t st   = smb + (uint32_t)(i & 3) * SB;
        const uint32_t stAh = st;
        const uint32_t stAl = st + 16384;
        const uint32_t stB  = st + NPASS * 16384u;

#pragma unroll
        for (int ks = 0; ks < 4; ks++) {
            uint32_t ah[2][4], al[2][4], bw[4][4];
            uint32_t aAddr[2], bAddr[4];
#pragma unroll
            for (int mt = 0; mt < 2; mt++) {
                const int r = wm * 32 + mt * 16 + lrowA;
                const int c = ks * 2 + lckA;
                aAddr[mt] = r * 128u + (uint32_t)(((c ^ (r & 7)) & 7) << 4);
            }
#pragma unroll
            for (int nt = 0; nt < 4; nt++) {
                const int r = wn * 64 + nt * 16 + lrowB;
                const int c = ks * 2 + lckB;
                bAddr[nt] = r * 128u + (uint32_t)(((c ^ (r & 7)) & 7) << 4);
            }
#pragma unroll
            for (int nt = 0; nt < 4; nt++) LDSM4(bw[nt], stB + bAddr[nt]);
            // pass 1: Ah * B
#pragma unroll
            for (int mt = 0; mt < 2; mt++) LDSM4(ah[mt], stAh + aAddr[mt]);
#pragma unroll
            for (int mt = 0; mt < 2; mt++)
#pragma unroll
                for (int n8 = 0; n8 < 8; n8++)
                    MMA16816(acc[mt][n8], ah[mt],
                             bw[n8 >> 1][(n8 & 1) * 2], bw[n8 >> 1][(n8 & 1) * 2 + 1]);
            // pass 2: Al * B
            if (NPASS == 2) {
#pragma unroll
                for (int mt = 0; mt < 2; mt++) LDSM4(al[mt], stAl + aAddr[mt]);
#pragma unroll
                for (int mt = 0; mt < 2; mt++)
#pragma unroll
                    for (int n8 = 0; n8 < 8; n8++)
                        MMA16816(acc[mt][n8], al[mt],
                                 bw[n8 >> 1][(n8 & 1) * 2], bw[n8 >> 1][(n8 & 1) * 2 + 1]);
            }
        }
        __syncthreads();
    }

    // ---- epilogue ----
    const int qrow = lane >> 2;
    const int qcol = (lane & 3) * 2;
#pragma unroll
    for (int mt = 0; mt < 2; mt++) {
#pragma unroll
        for (int h = 0; h < 2; h++) {
            const int row = bm + wm * 32 + mt * 16 + qrow + h * 8;
#pragma unroll
            for (int n8 = 0; n8 < 8; n8++) {
                const int col = bn + wn * 64 + n8 * 8 + qcol;
                float v0 = acc[mt][n8][h * 2 + 0] + bias[col];
                float v1 = acc[mt][n8][h * 2 + 1] + bias[col + 1];
                if (EPI == 0) {
                    v0 = gelu_exact(v0);
                    v1 = gelu_exact(v1);
                    __half h2[2], l2[2];
                    split_f16(v0, h2[0], l2[0]);
                    split_f16(v1, h2[1], l2[1]);
                    *(uint32_t*)(Chi + (size_t)row * N + col) = *(uint32_t*)h2;
                    *(uint32_t*)(Clo + (size_t)row * N + col) = *(uint32_t*)l2;
                } else {
                    if (EPI == 1) { v0 = gelu_exact(v0); v1 = gelu_exact(v1); }
                    float2 o = make_float2(v0, v1);
                    *(float2*)(Cf + (size_t)row * N + col) = o;
                }
            }
        }
    }
}

// ---------------------------------------------------------------------------
// Prep kernels
// ---------------------------------------------------------------------------
__global__ void conv_kernel(const float* __restrict__ in,
                            __half* __restrict__ hi, int n4)
{
    const int i = blockIdx.x * 256 + threadIdx.x;
    if (i >= n4) return;
    float4 v = ((const float4*)in)[i];
    __half h[4];
    h[0] = __float2half_rn(v.x); h[1] = __float2half_rn(v.y);
    h[2] = __float2half_rn(v.z); h[3] = __float2half_rn(v.w);
    ((uint2*)hi)[i] = *(uint2*)h;
}

__global__ void wtr_kernel(const float* __restrict__ w, int K, int N,
                           __half* __restrict__ t)
{
    const int i = blockIdx.x * 256 + threadIdx.x;
    if (i >= N * K) return;
    const int n = i / K, k = i - n * K;
    t[i] = __float2half_rn(w[(size_t)k * N + n]);
}

// combine: comb = inv_shift(hpre)*a0 + wbuf*a1, split to fp16 (C=512, groups 57)
__global__ void combine_kernel(const float* __restrict__ hpre,
                               const float* __restrict__ wbuf,
                               const float* __restrict__ a01,
                               __half* __restrict__ ohi,
                               __half* __restrict__ olo)
{
    const int m = blockIdx.x;
    const int b = m / TPB;
    const int y = (m / Wd) % Wd;
    const int x = m % Wd;
    const int c0 = threadIdx.x * 2;
#pragma unroll
    for (int j = 0; j < 2; j++) {
        const int c = c0 + j;
        const int g = c / 57;
        const int sh = c_sh[g], sw = c_sw[g];
        const int ys = y + sh, xs = x + sw;
        float hv = 0.0f;
        if ((unsigned)ys < 56u && (unsigned)xs < 56u)
            hv = hpre[(size_t)(m + sh * Wd + sw) * CIN + c];
        const float wv = wbuf[(size_t)m * CIN + c];
        const float a0 = a01[b * CIN + c];
        const float a1 = a01[2 * CIN + b * CIN + c];
        const float v = hv * a0 + wv * a1;
        __half h, l;
        split_f16(v, h, l);
        ohi[(size_t)m * CIN + c] = h;
        olo[(size_t)m * CIN + c] = l;
    }
}

// ---------------------------------------------------------------------------
// reduce + head (correctness-proven)
// ---------------------------------------------------------------------------
__global__ void reduce_kernel(const float* __restrict__ hpre,
                              const float* __restrict__ wbuf,
                              float* __restrict__ part)
{
    const int c = threadIdx.x;
    const int b = blockIdx.y;
    const int chunk = blockIdx.x;
    const int g = c / 57;
    const int sh = c_sh[g], sw = c_sw[g];
    float acc = 0.0f;
    const int m0 = b * TPB + chunk * 512;
    for (int it = 0; it < 512; it++) {
        const int m = m0 + it;
        const int y = (m / Wd) % Wd;
        const int x = m % Wd;
        const int ys = y + sh, xs = x + sw;
        float hv = 0.0f;
        if ((unsigned)ys < 56u && (unsigned)xs < 56u)
            hv = hpre[(size_t)(m + sh * Wd + sw) * CIN + c];
        acc += hv + wbuf[(size_t)m * CIN + c];
    }
    part[(size_t)(b * RED_CHUNKS + chunk) * CIN + c] = acc;
}

__global__ void head_kernel(const float* __restrict__ part,
                            const float* __restrict__ rw1_w,
                            const float* __restrict__ rw1_b,
                            const float* __restrict__ rw2_w,
                            const float* __restrict__ rw2_b,
                            float* __restrict__ a01)
{
    __shared__ float s_in[512];
    __shared__ float s_t1[128];
    __shared__ float s_t2[1024];
    const int tid = threadIdx.x;
    for (int b = 0; b < 2; b++) {
        float s = 0.0f;
        for (int p = 0; p < RED_CHUNKS; p++)
            s += part[(size_t)(b * RED_CHUNKS + p) * CIN + tid];
        s_in[tid] = s * (1.0f / (float)TPB);
        __syncthreads();
        if (tid < 128) {
            float acc = rw1_b[tid];
            for (int c = 0; c < 512; c++)
                acc = fmaf(s_in[c], rw1_w[c * 128 + tid], acc);
            s_t1[tid] = gelu_exact(acc);
        }
        __syncthreads();
        for (int n = tid; n < 1024; n += 512) {
            float acc = rw2_b[n];
            for (int j = 0; j < 128; j++)
                acc = fmaf(s_t1[j], rw2_w[j * 1024 + n], acc);
            s_t2[n] = acc;
        }
        __syncthreads();
        {
            const float v0 = s_t2[2 * tid];
            const float v1 = s_t2[2 * tid + 1];
            const float mx = fmaxf(v0, v1);
            const float e0 = expf(v0 - mx);
            const float e1 = expf(v1 - mx);
            const float inv = 1.0f / (e0 + e1);
            a01[b * CIN + tid]           = e0 * inv;
            a01[2 * CIN + b * CIN + tid] = e1 * inv;
        }
        __syncthreads();
    }
}

// ---------------------------------------------------------------------------
extern "C" void kernel_launch(void* const* d_in, const int* in_sizes, int n_in,
                              void* d_out, int out_size)
{
    const float* x      = (const float*)d_in[0];
    const float* fc_w   = (const float*)d_in[1];
    const float* fc_b   = (const float*)d_in[2];
    const float* fc1_w  = (const float*)d_in[3];
    const float* fc1_b  = (const float*)d_in[4];
    const float* fc2_w  = (const float*)d_in[5];
    const float* fc2_b  = (const float*)d_in[6];
    const float* rw1_w  = (const float*)d_in[7];
    const float* rw1_b  = (const float*)d_in[8];
    const float* rw2_w  = (const float*)d_in[9];
    const float* rw2_b  = (const float*)d_in[10];
    const float* proj_w = (const float*)d_in[11];
    const float* proj_b = (const float*)d_in[12];
    float* out = (float*)d_out;

    __half *xhi, *xhhi, *xhlo, *cmhi, *cmlo, *w1, *w2, *w3, *w4;
    float *hpre, *wbuf, *part, *a01;
    cudaGetSymbolAddress((void**)&xhi,  g_xhi);
    cudaGetSymbolAddress((void**)&xhhi, g_xhhi); cudaGetSymbolAddress((void**)&xhlo, g_xhlo);
    cudaGetSymbolAddress((void**)&cmhi, g_cmhi); cudaGetSymbolAddress((void**)&cmlo, g_cmlo);
    cudaGetSymbolAddress((void**)&w1, g_w1); cudaGetSymbolAddress((void**)&w2, g_w2);
    cudaGetSymbolAddress((void**)&w3, g_w3); cudaGetSymbolAddress((void**)&w4, g_w4);
    cudaGetSymbolAddress((void**)&hpre, g_hpre); cudaGetSymbolAddress((void**)&wbuf, g_wbuf);
    cudaGetSymbolAddress((void**)&part, g_part); cudaGetSymbolAddress((void**)&a01,  g_a01);

    const int SM1 = 4 * 2 * 16384;   // NPASS=1: (1+1) tiles/stage
    const int SM2 = 4 * 3 * 16384;   // NPASS=2: (2+1) tiles/stage
    cudaFuncSetAttribute(mma_gemm<0,1,0>, cudaFuncAttributeMaxDynamicSharedMemorySize, SM1);
    cudaFuncSetAttribute(mma_gemm<1,2,1>, cudaFuncAttributeMaxDynamicSharedMemorySize, SM2);
    cudaFuncSetAttribute(mma_gemm<1,2,0>, cudaFuncAttributeMaxDynamicSharedMemorySize, SM2);
    cudaFuncSetAttribute(mma_gemm<2,2,0>, cudaFuncAttributeMaxDynamicSharedMemorySize, SM2);

    // weights: transpose -> fp16 [N][K]
    wtr_kernel<<<(HIDN * CIN + 255) / 256, 256>>>(fc_w,  CIN,  HIDN, w1);
    wtr_kernel<<<(CIN * HIDN + 255) / 256, 256>>>(fc1_w, HIDN, CIN,  w2);
    wtr_kernel<<<(CIN * HIDN + 255) / 256, 256>>>(fc2_w, HIDN, CIN,  w3);
    wtr_kernel<<<(CIN * CIN  + 255) / 256, 256>>>(proj_w, CIN, CIN,  w4);

    // x -> fp16 (single precision digit; GEMM-1 is 1-pass)
    conv_kernel<<<(NTOK * CIN / 4 + 255) / 256, 256>>>(x, xhi, NTOK * CIN / 4);

    // 1) xh = gelu(x @ fc_w + b) -> fp16 hi/lo   [50176,1024]  (1-pass A)
    mma_gemm<0,1,0><<<dim3(HIDN / 128, NTOK / 128), 256, SM1>>>(
        xhi, nullptr, w1, fc_b, HIDN, CIN, nullptr, xhhi, xhlo);

    // 2) hpre = gelu(shift_fwd(xh) @ fc1_w + b) -> f32   (shift fused in loads)
    mma_gemm<1,2,1><<<dim3(CIN / 128, NTOK / 128), 256, SM2>>>(
        xhhi, xhlo, w2, fc1_b, CIN, HIDN, hpre, nullptr, nullptr);

    // 3) wbuf = gelu(xh @ fc2_w + b) -> f32
    mma_gemm<1,2,0><<<dim3(CIN / 128, NTOK / 128), 256, SM2>>>(
        xhhi, xhlo, w3, fc2_b, CIN, HIDN, wbuf, nullptr, nullptr);

    // 4) mean over tokens + head MLP + pairwise softmax
    reduce_kernel<<<dim3(RED_CHUNKS, 2), 512>>>(hpre, wbuf, part);
    head_kernel<<<1, 512>>>(part, rw1_w, rw1_b, rw2_w, rw2_b, a01);

    // 5) comb = h*a0 + w*a1 -> fp16 hi/lo
    combine_kernel<<<NTOK, 256>>>(hpre, wbuf, a01, cmhi, cmlo);

    // 6) out = comb @ proj_w + proj_b -> f32
    mma_gemm<2,2,0><<<dim3(CIN / 128, NTOK / 128), 256, SM2>>>(
        cmhi, cmlo, w4, proj_b, CIN, CIN, out, nullptr, nullptr);
}

// round 13
// speedup vs baseline: 5.2464x; 1.3042x over previous
#include <cuda_runtime.h>
#include <cuda_fp16.h>
#include <math.h>
#include <cstdint>

// ---------------------------------------------------------------------------
// Shapes: B=2, T=8, H=W=56, C=512, HID=1024. NTOK = 50176.
// ---------------------------------------------------------------------------
#define NTOK 50176
#define TPB  25088
#define Wd   56
#define CIN  512
#define HIDN 1024
#define RED_CHUNKS 49

// ---------------------------------------------------------------------------
// Scratch (__device__ globals; allocation-free rule). 128B aligned for cp.async.
// All GEMM operands single fp16 (1-pass; measured ~2.1e-4 error per A-quant).
// ---------------------------------------------------------------------------
__device__ __align__(128) __half g_xhi [(size_t)NTOK * CIN];    // x -> fp16
__device__ __align__(128) __half g_xh  [(size_t)NTOK * HIDN];   // gelu(x@fc_w+b)
__device__ __align__(128) float  g_hpre[(size_t)NTOK * CIN];
__device__ __align__(128) float  g_wbuf[(size_t)NTOK * CIN];
__device__ __align__(128) __half g_cm  [(size_t)NTOK * CIN];    // h*a0 + w*a1
__device__ __align__(128) __half g_w1[HIDN * CIN];   // fc_w^T
__device__ __align__(128) __half g_w2[CIN * HIDN];   // fc1_w^T
__device__ __align__(128) __half g_w3[CIN * HIDN];   // fc2_w^T
__device__ __align__(128) __half g_w4[CIN * CIN];    // proj_w^T
__device__ float g_part[2 * RED_CHUNKS * CIN];
__device__ float g_a01 [4 * CIN];

__constant__ int c_sh[9] = { 1, 1, 1, 0, 0, 0,-1,-1,-1};
__constant__ int c_sw[9] = { 1, 0,-1, 1, 0,-1, 1, 0,-1};

__device__ __forceinline__ float gelu_exact(float v) {
    return 0.5f * v * (1.0f + erff(v * 0.70710678118654752f));
}
__device__ __forceinline__ uint32_t smem_u32(const void* p) {
    uint32_t a;
    asm("{ .reg .u64 t; cvta.to.shared.u64 t, %1; cvt.u32.u64 %0, t; }" : "=r"(a) : "l"(p));
    return a;
}

#define CP_ASYNC16(dst, src) \
    asm volatile("cp.async.cg.shared.global [%0], [%1], 16;" :: "r"(dst), "l"(src) : "memory")
// 4-byte cp.async with zero-fill when n==0 (ignore-src form)
#define CP_ASYNC4Z(dst, src, n) \
    asm volatile("cp.async.ca.shared.global [%0], [%1], 4, %2;" :: "r"(dst), "l"(src), "r"(n) : "memory")
#define CP_COMMIT() asm volatile("cp.async.commit_group;" ::: "memory")

#define LDSM4(r, a) \
    asm volatile("ldmatrix.sync.aligned.m8n8.x4.shared.b16 {%0,%1,%2,%3}, [%4];" \
        : "=r"((r)[0]), "=r"((r)[1]), "=r"((r)[2]), "=r"((r)[3]) : "r"(a))

#define MMA16816(d, a, b0, b1) \
    asm volatile("mma.sync.aligned.m16n8k16.row.col.f32.f16.f16.f32 " \
        "{%0,%1,%2,%3}, {%4,%5,%6,%7}, {%8,%9}, {%0,%1,%2,%3};" \
        : "+f"((d)[0]), "+f"((d)[1]), "+f"((d)[2]), "+f"((d)[3]) \
        : "r"((a)[0]), "r"((a)[1]), "r"((a)[2]), "r"((a)[3]), "r"(b0), "r"(b1))

// ---------------------------------------------------------------------------
// HMMA GEMM (single-pass fp16): C[M,N] = epi(A@W + bias), A [M,K], W^T [N,K].
//   SHIFT=1: forward patch-shift fused into A-tile loads via 4B zfill cp.async
//            (K=1024, channel groups of 114; even boundaries => no straddle).
// CTA 128x128, warps 4(m)x2(n), warp tile 32x64, K-chunk 64, 4-stage cp.async.
// Stage = A tile (16KB) + B tile (16KB) = 32KB.
// EPI 0: gelu -> fp16.  EPI 1: gelu -> f32.  EPI 2: bias only -> f32.
// ---------------------------------------------------------------------------
#define STAGE_BYTES 32768u
#define GEMM_SMEM   (4 * 32768)

template <int EPI, int SHIFT>
__global__ __launch_bounds__(256, 1)
void mma_gemm(const __half* __restrict__ A, const __half* __restrict__ Bw,
              const float* __restrict__ bias, int N, int K,
              float* __restrict__ Cf, __half* __restrict__ Ch)
{
    extern __shared__ char smraw[];
    const uint32_t smb = smem_u32(smraw);

    const int tid  = threadIdx.x;
    const int wid  = tid >> 5;
    const int lane = tid & 31;
    const int wm   = wid & 3;
    const int wn   = wid >> 2;
    const int bm   = blockIdx.y * 128;
    const int bn   = blockIdx.x * 128;

    const __half* p0 = A  + (size_t)bm * K;
    const __half* p2 = Bw + (size_t)bn * K;

    const int lrowA = lane & 15;
    const int lckA  = lane >> 4;
    const int lrowB = (lane & 7) + ((lane & 16) >> 1);
    const int lckB  = (lane >> 3) & 1;

    float acc[2][8][4];
#pragma unroll
    for (int i = 0; i < 2; i++)
#pragma unroll
        for (int j = 0; j < 8; j++)
#pragma unroll
            for (int q = 0; q < 4; q++) acc[i][j][q] = 0.0f;

    const int NC = K >> 6;

    auto issue = [&](int ci) {
        const uint32_t st_ = smb + (uint32_t)(ci & 3) * STAGE_BYTES;
        const int kt_ = ci * 64;
        // B tile via 16B chunks (slot 1)
#pragma unroll
        for (int t = 0; t < 4; t++) {
            const int row = t * 32 + (tid >> 3);
            const __half* src = p2 + (size_t)row * K + kt_ + (tid & 7) * 8;
            const uint32_t dst = st_ + 16384u + row * 128u
                + (uint32_t)(((tid & 7) ^ (row & 7)) << 4);
            CP_ASYNC16(dst, src);
        }
        if (SHIFT == 0) {
            // A tile via 16B chunks (slot 0)
#pragma unroll
            for (int t = 0; t < 4; t++) {
                const int row = t * 32 + (tid >> 3);
                const __half* src = p0 + (size_t)row * K + kt_ + (tid & 7) * 8;
                const uint32_t dst = st_ + row * 128u
                    + (uint32_t)(((tid & 7) ^ (row & 7)) << 4);
                CP_ASYNC16(dst, src);
            }
        } else {
            // A via 4B zfill with fused forward shift; thread owns column pair.
            const int cA   = tid & 31;
            const int kcol = kt_ + 2 * cA;
            const int g    = kcol / 114;
            const int sh   = c_sh[g], sw = c_sw[g];
            const int roff = sh * Wd + sw;
            const uint32_t dbase = (uint32_t)((cA & 3) * 4);
#pragma unroll
            for (int t = 0; t < 16; t++) {
                const int row = t * 8 + (tid >> 5);
                const int m = bm + row;
                const int y = (m / Wd) % Wd;
                const int x = m % Wd;
                const int ys = y - sh, xs = x - sw;
                const bool val = ((unsigned)ys < 56u) && ((unsigned)xs < 56u);
                const int srow = val ? (row - roff) : row;
                const int nbytes = val ? 4 : 0;
                const uint32_t dst = st_ + row * 128u
                    + (uint32_t)((((cA >> 2) ^ (row & 7)) << 4)) + dbase;
                CP_ASYNC4Z(dst, p0 + (size_t)srow * K + kcol, nbytes);
            }
        }
        CP_COMMIT();
    };

    issue(0);
    issue(1);
    issue(2);

    for (int i = 0; i < NC; i++) {
        // In-flight groups: chunks i .. min(i+2, NC-1). Guarantee group i landed.
        const int rem = NC - 1 - i;
        if (rem >= 2)      asm volatile("cp.async.wait_group 2;" ::: "memory");
        else if (rem == 1) asm volatile("cp.async.wait_group 1;" ::: "memory");
        else               asm volatile("cp.async.wait_group 0;" ::: "memory");
        __syncthreads();
        if (i + 3 < NC) issue(i + 3);

        const uint32_t stA = smb + (uint32_t)(i & 3) * STAGE_BYTES;
        const uint32_t stB = stA + 16384u;

#pragma unroll
        for (int ks = 0; ks < 4; ks++) {
            uint32_t ah[2][4], bw[4][4];
#pragma unroll
            for (int nt = 0; nt < 4; nt++) {
                const int r = wn * 64 + nt * 16 + lrowB;
                const int c = ks * 2 + lckB;
                LDSM4(bw[nt], stB + r * 128u + (uint32_t)(((c ^ (r & 7)) & 7) << 4));
            }
#pragma unroll
            for (int mt = 0; mt < 2; mt++) {
                const int r = wm * 32 + mt * 16 + lrowA;
                const int c = ks * 2 + lckA;
                LDSM4(ah[mt], stA + r * 128u + (uint32_t)(((c ^ (r & 7)) & 7) << 4));
            }
#pragma unroll
            for (int mt = 0; mt < 2; mt++)
#pragma unroll
                for (int n8 = 0; n8 < 8; n8++)
                    MMA16816(acc[mt][n8], ah[mt],
                             bw[n8 >> 1][(n8 & 1) * 2], bw[n8 >> 1][(n8 & 1) * 2 + 1]);
        }
        __syncthreads();
    }

    // ---- epilogue ----
    const int qrow = lane >> 2;
    const int qcol = (lane & 3) * 2;
#pragma unroll
    for (int mt = 0; mt < 2; mt++) {
#pragma unroll
        for (int h = 0; h < 2; h++) {
            const int row = bm + wm * 32 + mt * 16 + qrow + h * 8;
#pragma unroll
            for (int n8 = 0; n8 < 8; n8++) {
                const int col = bn + wn * 64 + n8 * 8 + qcol;
                float v0 = acc[mt][n8][h * 2 + 0] + bias[col];
                float v1 = acc[mt][n8][h * 2 + 1] + bias[col + 1];
                if (EPI == 0) {
                    __half h2[2];
                    h2[0] = __float2half_rn(gelu_exact(v0));
                    h2[1] = __float2half_rn(gelu_exact(v1));
                    *(uint32_t*)(Ch + (size_t)row * N + col) = *(uint32_t*)h2;
                } else {
                    if (EPI == 1) { v0 = gelu_exact(v0); v1 = gelu_exact(v1); }
                    float2 o = make_float2(v0, v1);
                    *(float2*)(Cf + (size_t)row * N + col) = o;
                }
            }
        }
    }
}

// ---------------------------------------------------------------------------
// Prep kernels
// ---------------------------------------------------------------------------
__global__ void conv_kernel(const float* __restrict__ in,
                            __half* __restrict__ hi, int n4)
{
    const int i = blockIdx.x * 256 + threadIdx.x;
    if (i >= n4) return;
    float4 v = ((const float4*)in)[i];
    __half h[4];
    h[0] = __float2half_rn(v.x); h[1] = __float2half_rn(v.y);
    h[2] = __float2half_rn(v.z); h[3] = __float2half_rn(v.w);
    ((uint2*)hi)[i] = *(uint2*)h;
}

__global__ void wtr_kernel(const float* __restrict__ w, int K, int N,
                           __half* __restrict__ t)
{
    const int i = blockIdx.x * 256 + threadIdx.x;
    if (i >= N * K) return;
    const int n = i / K, k = i - n * K;
    t[i] = __float2half_rn(w[(size_t)k * N + n]);
}

// combine: cm = inv_shift(hpre)*a0 + wbuf*a1 -> fp16 (C=512, groups 57)
__global__ void combine_kernel(const float* __restrict__ hpre,
                               const float* __restrict__ wbuf,
                               const float* __restrict__ a01,
                               __half* __restrict__ oh)
{
    const int m = blockIdx.x;
    const int b = m / TPB;
    const int y = (m / Wd) % Wd;
    const int x = m % Wd;
    const int c0 = threadIdx.x * 2;
#pragma unroll
    for (int j = 0; j < 2; j++) {
        const int c = c0 + j;
        const int g = c / 57;
        const int sh = c_sh[g], sw = c_sw[g];
        const int ys = y + sh, xs = x + sw;
        float hv = 0.0f;
        if ((unsigned)ys < 56u && (unsigned)xs < 56u)
            hv = hpre[(size_t)(m + sh * Wd + sw) * CIN + c];
        const float wv = wbuf[(size_t)m * CIN + c];
        const float a0 = a01[b * CIN + c];
        const float a1 = a01[2 * CIN + b * CIN + c];
        oh[(size_t)m * CIN + c] = __float2half_rn(hv * a0 + wv * a1);
    }
}

// ---------------------------------------------------------------------------
// reduce + head (correctness-proven)
// ---------------------------------------------------------------------------
__global__ void reduce_kernel(const float* __restrict__ hpre,
                              const float* __restrict__ wbuf,
                              float* __restrict__ part)
{
    const int c = threadIdx.x;
    const int b = blockIdx.y;
    const int chunk = blockIdx.x;
    const int g = c / 57;
    const int sh = c_sh[g], sw = c_sw[g];
    float acc = 0.0f;
    const int m0 = b * TPB + chunk * 512;
    for (int it = 0; it < 512; it++) {
        const int m = m0 + it;
        const int y = (m / Wd) % Wd;
        const int x = m % Wd;
        const int ys = y + sh, xs = x + sw;
        float hv = 0.0f;
        if ((unsigned)ys < 56u && (unsigned)xs < 56u)
            hv = hpre[(size_t)(m + sh * Wd + sw) * CIN + c];
        acc += hv + wbuf[(size_t)m * CIN + c];
    }
    part[(size_t)(b * RED_CHUNKS + chunk) * CIN + c] = acc;
}

__global__ void head_kernel(const float* __restrict__ part,
                            const float* __restrict__ rw1_w,
                            const float* __restrict__ rw1_b,
                            const float* __restrict__ rw2_w,
                            const float* __restrict__ rw2_b,
                            float* __restrict__ a01)
{
    __shared__ float s_in[512];
    __shared__ float s_t1[128];
    __shared__ float s_t2[1024];
    const int tid = threadIdx.x;
    for (int b = 0; b < 2; b++) {
        float s = 0.0f;
        for (int p = 0; p < RED_CHUNKS; p++)
            s += part[(size_t)(b * RED_CHUNKS + p) * CIN + tid];
        s_in[tid] = s * (1.0f / (float)TPB);
        __syncthreads();
        if (tid < 128) {
            float acc = rw1_b[tid];
            for (int c = 0; c < 512; c++)
                acc = fmaf(s_in[c], rw1_w[c * 128 + tid], acc);
            s_t1[tid] = gelu_exact(acc);
        }
        __syncthreads();
        for (int n = tid; n < 1024; n += 512) {
            float acc = rw2_b[n];
            for (int j = 0; j < 128; j++)
                acc = fmaf(s_t1[j], rw2_w[j * 1024 + n], acc);
            s_t2[n] = acc;
        }
        __syncthreads();
        {
            const float v0 = s_t2[2 * tid];
            const float v1 = s_t2[2 * tid + 1];
            const float mx = fmaxf(v0, v1);
            const float e0 = expf(v0 - mx);
            const float e1 = expf(v1 - mx);
            const float inv = 1.0f / (e0 + e1);
            a01[b * CIN + tid]           = e0 * inv;
            a01[2 * CIN + b * CIN + tid] = e1 * inv;
        }
        __syncthreads();
    }
}

// ---------------------------------------------------------------------------
extern "C" void kernel_launch(void* const* d_in, const int* in_sizes, int n_in,
                              void* d_out, int out_size)
{
    const float* x      = (const float*)d_in[0];
    const float* fc_w   = (const float*)d_in[1];
    const float* fc_b   = (const float*)d_in[2];
    const float* fc1_w  = (const float*)d_in[3];
    const float* fc1_b  = (const float*)d_in[4];
    const float* fc2_w  = (const float*)d_in[5];
    const float* fc2_b  = (const float*)d_in[6];
    const float* rw1_w  = (const float*)d_in[7];
    const float* rw1_b  = (const float*)d_in[8];
    const float* rw2_w  = (const float*)d_in[9];
    const float* rw2_b  = (const float*)d_in[10];
    const float* proj_w = (const float*)d_in[11];
    const float* proj_b = (const float*)d_in[12];
    float* out = (float*)d_out;

    __half *xhi, *xh, *cm, *w1, *w2, *w3, *w4;
    float *hpre, *wbuf, *part, *a01;
    cudaGetSymbolAddress((void**)&xhi,  g_xhi);
    cudaGetSymbolAddress((void**)&xh,   g_xh);
    cudaGetSymbolAddress((void**)&cm,   g_cm);
    cudaGetSymbolAddress((void**)&w1, g_w1); cudaGetSymbolAddress((void**)&w2, g_w2);
    cudaGetSymbolAddress((void**)&w3, g_w3); cudaGetSymbolAddress((void**)&w4, g_w4);
    cudaGetSymbolAddress((void**)&hpre, g_hpre); cudaGetSymbolAddress((void**)&wbuf, g_wbuf);
    cudaGetSymbolAddress((void**)&part, g_part); cudaGetSymbolAddress((void**)&a01,  g_a01);

    cudaFuncSetAttribute(mma_gemm<0,0>, cudaFuncAttributeMaxDynamicSharedMemorySize, GEMM_SMEM);
    cudaFuncSetAttribute(mma_gemm<1,1>, cudaFuncAttributeMaxDynamicSharedMemorySize, GEMM_SMEM);
    cudaFuncSetAttribute(mma_gemm<1,0>, cudaFuncAttributeMaxDynamicSharedMemorySize, GEMM_SMEM);
    cudaFuncSetAttribute(mma_gemm<2,0>, cudaFuncAttributeMaxDynamicSharedMemorySize, GEMM_SMEM);

    // weights: transpose -> fp16 [N][K]
    wtr_kernel<<<(HIDN * CIN + 255) / 256, 256>>>(fc_w,  CIN,  HIDN, w1);
    wtr_kernel<<<(CIN * HIDN + 255) / 256, 256>>>(fc1_w, HIDN, CIN,  w2);
    wtr_kernel<<<(CIN * HIDN + 255) / 256, 256>>>(fc2_w, HIDN, CIN,  w3);
    wtr_kernel<<<(CIN * CIN  + 255) / 256, 256>>>(proj_w, CIN, CIN,  w4);

    // x -> fp16
    conv_kernel<<<(NTOK * CIN / 4 + 255) / 256, 256>>>(x, xhi, NTOK * CIN / 4);

    // 1) xh = gelu(x @ fc_w + b) -> fp16   [50176,1024]
    mma_gemm<0,0><<<dim3(HIDN / 128, NTOK / 128), 256, GEMM_SMEM>>>(
        xhi, w1, fc_b, HIDN, CIN, nullptr, xh);

    // 2) hpre = gelu(shift_fwd(xh) @ fc1_w + b) -> f32   (shift fused in loads)
    mma_gemm<1,1><<<dim3(CIN / 128, NTOK / 128), 256, GEMM_SMEM>>>(
        xh, w2, fc1_b, CIN, HIDN, hpre, nullptr);

    // 3) wbuf = gelu(xh @ fc2_w + b) -> f32
    mma_gemm<1,0><<<dim3(CIN / 128, NTOK / 128), 256, GEMM_SMEM>>>(
        xh, w3, fc2_b, CIN, HIDN, wbuf, nullptr);

    // 4) mean over tokens + head MLP + pairwise softmax
    reduce_kernel<<<dim3(RED_CHUNKS, 2), 512>>>(hpre, wbuf, part);
    head_kernel<<<1, 512>>>(part, rw1_w, rw1_b, rw2_w, rw2_b, a01);

    // 5) cm = h*a0 + w*a1 -> fp16
    combine_kernel<<<NTOK, 256>>>(hpre, wbuf, a01, cm);

    // 6) out = cm @ proj_w + proj_b -> f32
    mma_gemm<2,0><<<dim3(CIN / 128, NTOK / 128), 256, GEMM_SMEM>>>(
        cm, w4, proj_b, CIN, CIN, out, nullptr);
}

// round 16
// speedup vs baseline: 5.4852x; 1.0455x over previous
#include <cuda_runtime.h>
#include <cuda_fp16.h>
#include <math.h>
#include <cstdint>

// ---------------------------------------------------------------------------
// Shapes: B=2, T=8, H=W=56, C=512, HID=1024. NTOK = 50176.
// ---------------------------------------------------------------------------
#define NTOK 50176
#define TPB  25088
#define Wd   56
#define CIN  512
#define HIDN 1024
#define RED_CHUNKS 49

// ---------------------------------------------------------------------------
// Scratch (__device__ globals; allocation-free rule). 128B aligned for cp.async.
// ---------------------------------------------------------------------------
__device__ __align__(128) __half g_xhi [(size_t)NTOK * CIN];    // x -> fp16
__device__ __align__(128) __half g_xh  [(size_t)NTOK * HIDN];   // gelu(x@fc_w+b)
__device__ __align__(128) float  g_hpre[(size_t)NTOK * CIN];
__device__ __align__(128) float  g_wbuf[(size_t)NTOK * CIN];
__device__ __align__(128) __half g_cm  [(size_t)NTOK * CIN];    // h*a0 + w*a1
__device__ __align__(128) __half g_w1[HIDN * CIN];   // fc_w^T
__device__ __align__(128) __half g_w2[CIN * HIDN];   // fc1_w^T
__device__ __align__(128) __half g_w3[CIN * HIDN];   // fc2_w^T
__device__ __align__(128) __half g_w4[CIN * CIN];    // proj_w^T
__device__ float g_part[2 * RED_CHUNKS * CIN];
__device__ float g_a01 [4 * CIN];

__constant__ int c_sh[9] = { 1, 1, 1, 0, 0, 0,-1,-1,-1};
__constant__ int c_sw[9] = { 1, 0,-1, 1, 0,-1, 1, 0,-1};

__device__ __forceinline__ float gelu_exact(float v) {
    return 0.5f * v * (1.0f + erff(v * 0.70710678118654752f));
}
__device__ __forceinline__ uint32_t smem_u32(const void* p) {
    uint32_t a;
    asm("{ .reg .u64 t; cvta.to.shared.u64 t, %1; cvt.u32.u64 %0, t; }" : "=r"(a) : "l"(p));
    return a;
}

#define CP_ASYNC16(dst, src) \
    asm volatile("cp.async.cg.shared.global [%0], [%1], 16;" :: "r"(dst), "l"(src) : "memory")
// 4-byte cp.async with zero-fill when n==0 (ignore-src form)
#define CP_ASYNC4Z(dst, src, n) \
    asm volatile("cp.async.ca.shared.global [%0], [%1], 4, %2;" :: "r"(dst), "l"(src), "r"(n) : "memory")
#define CP_COMMIT() asm volatile("cp.async.commit_group;" ::: "memory")

#define LDSM4(r, a) \
    asm volatile("ldmatrix.sync.aligned.m8n8.x4.shared.b16 {%0,%1,%2,%3}, [%4];" \
        : "=r"((r)[0]), "=r"((r)[1]), "=r"((r)[2]), "=r"((r)[3]) : "r"(a))

#define MMA16816(d, a, b0, b1) \
    asm volatile("mma.sync.aligned.m16n8k16.row.col.f32.f16.f16.f32 " \
        "{%0,%1,%2,%3}, {%4,%5,%6,%7}, {%8,%9}, {%0,%1,%2,%3};" \
        : "+f"((d)[0]), "+f"((d)[1]), "+f"((d)[2]), "+f"((d)[3]) \
        : "r"((a)[0]), "r"((a)[1]), "r"((a)[2]), "r"((a)[3]), "r"(b0), "r"(b1))

// ---------------------------------------------------------------------------
// HMMA GEMM (single-pass fp16): C[M,N] = epi(A@W + bias), A [M,K], W^T [N,K].
//   SHIFT=1: forward patch-shift fused into A-tile loads via 4B zfill cp.async.
// CTA tile 128(m) x 256(n). 8 warps in 2(m) x 4(n); warp tile 64x64.
// Per k16 step: 8 LDSM : 32 MMA (was 6:16) -> less LDSM/issue overhead.
// K-chunk 64, 4-stage cp.async. Stage = A 16KB + B 32KB = 48KB.
// EPI 0: gelu -> fp16.  EPI 1: gelu -> f32.  EPI 2: bias only -> f32.
// ---------------------------------------------------------------------------
#define STAGE_BYTES 49152u
#define GEMM_SMEM   (4 * 49152)

template <int EPI, int SHIFT>
__global__ __launch_bounds__(256, 1)
void mma_gemm(const __half* __restrict__ A, const __half* __restrict__ Bw,
              const float* __restrict__ bias, int N, int K,
              float* __restrict__ Cf, __half* __restrict__ Ch)
{
    extern __shared__ char smraw[];
    const uint32_t smb = smem_u32(smraw);

    const int tid  = threadIdx.x;
    const int wid  = tid >> 5;
    const int lane = tid & 31;
    const int wm   = wid & 1;        // m offset wm*64
    const int wn   = wid >> 1;       // n offset wn*64
    const int bm   = blockIdx.y * 128;
    const int bn   = blockIdx.x * 256;

    const __half* p0 = A  + (size_t)bm * K;
    const __half* p2 = Bw + (size_t)bn * K;

    const int lrowA = lane & 15;
    const int lckA  = lane >> 4;
    const int lrowB = (lane & 7) + ((lane & 16) >> 1);
    const int lckB  = (lane >> 3) & 1;

    float acc[4][8][4];
#pragma unroll
    for (int i = 0; i < 4; i++)
#pragma unroll
        for (int j = 0; j < 8; j++)
#pragma unroll
            for (int q = 0; q < 4; q++) acc[i][j][q] = 0.0f;

    const int NC = K >> 6;

    auto issue = [&](int ci) {
        const uint32_t st_ = smb + (uint32_t)(ci & 3) * STAGE_BYTES;
        const int kt_ = ci * 64;
        // B tile: 256 rows x 128B at slot 16KB (8 x 16B chunks per thread)
#pragma unroll
        for (int t = 0; t < 8; t++) {
            const int row = t * 32 + (tid >> 3);
            const __half* src = p2 + (size_t)row * K + kt_ + (tid & 7) * 8;
            const uint32_t dst = st_ + 16384u + row * 128u
                + (uint32_t)(((tid & 7) ^ (row & 7)) << 4);
            CP_ASYNC16(dst, src);
        }
        if (SHIFT == 0) {
            // A tile: 128 rows x 128B at slot 0 (4 x 16B chunks per thread)
#pragma unroll
            for (int t = 0; t < 4; t++) {
                const int row = t * 32 + (tid >> 3);
                const __half* src = p0 + (size_t)row * K + kt_ + (tid & 7) * 8;
                const uint32_t dst = st_ + row * 128u
                    + (uint32_t)(((tid & 7) ^ (row & 7)) << 4);
                CP_ASYNC16(dst, src);
            }
        } else {
            // A via 4B zfill with fused forward shift; thread owns column pair.
            const int cA   = tid & 31;
            const int kcol = kt_ + 2 * cA;
            const int g    = kcol / 114;
            const int sh   = c_sh[g], sw = c_sw[g];
            const int roff = sh * Wd + sw;
            const uint32_t dbase = (uint32_t)((cA & 3) * 4);
#pragma unroll
            for (int t = 0; t < 16; t++) {
                const int row = t * 8 + (tid >> 5);
                const int m = bm + row;
                const int y = (m / Wd) % Wd;
                const int x = m % Wd;
                const int ys = y - sh, xs = x - sw;
                const bool val = ((unsigned)ys < 56u) && ((unsigned)xs < 56u);
                const int srow = val ? (row - roff) : row;
                const int nbytes = val ? 4 : 0;
                const uint32_t dst = st_ + row * 128u
                    + (uint32_t)((((cA >> 2) ^ (row & 7)) << 4)) + dbase;
                CP_ASYNC4Z(dst, p0 + (size_t)srow * K + kcol, nbytes);
            }
        }
        CP_COMMIT();
    };

    issue(0);
    issue(1);
    issue(2);

    for (int i = 0; i < NC; i++) {
        // In-flight groups: chunks i .. min(i+2, NC-1). Guarantee group i landed.
        const int rem = NC - 1 - i;
        if (rem >= 2)      asm volatile("cp.async.wait_group 2;" ::: "memory");
        else if (rem == 1) asm volatile("cp.async.wait_group 1;" ::: "memory");
        else               asm volatile("cp.async.wait_group 0;" ::: "memory");
        __syncthreads();
        if (i + 3 < NC) issue(i + 3);

        const uint32_t stA = smb + (uint32_t)(i & 3) * STAGE_BYTES;
        const uint32_t stB = stA + 16384u;

#pragma unroll
        for (int ks = 0; ks < 4; ks++) {
            uint32_t ah[4][4], bw[4][4];
#pragma unroll
            for (int nt = 0; nt < 4; nt++) {
                const int r = wn * 64 + nt * 16 + lrowB;
                const int c = ks * 2 + lckB;
                LDSM4(bw[nt], stB + r * 128u + (uint32_t)(((c ^ (r & 7)) & 7) << 4));
            }
#pragma unroll
            for (int mt = 0; mt < 4; mt++) {
                const int r = wm * 64 + mt * 16 + lrowA;
                const int c = ks * 2 + lckA;
                LDSM4(ah[mt], stA + r * 128u + (uint32_t)(((c ^ (r & 7)) & 7) << 4));
            }
#pragma unroll
            for (int mt = 0; mt < 4; mt++)
#pragma unroll
                for (int n8 = 0; n8 < 8; n8++)
                    MMA16816(acc[mt][n8], ah[mt],
                             bw[n8 >> 1][(n8 & 1) * 2], bw[n8 >> 1][(n8 & 1) * 2 + 1]);
        }
        __syncthreads();
    }

    // ---- epilogue ----
    const int qrow = lane >> 2;
    const int qcol = (lane & 3) * 2;
#pragma unroll
    for (int mt = 0; mt < 4; mt++) {
#pragma unroll
        for (int h = 0; h < 2; h++) {
            const int row = bm + wm * 64 + mt * 16 + qrow + h * 8;
#pragma unroll
            for (int n8 = 0; n8 < 8; n8++) {
                const int col = bn + wn * 64 + n8 * 8 + qcol;
                float v0 = acc[mt][n8][h * 2 + 0] + bias[col];
                float v1 = acc[mt][n8][h * 2 + 1] + bias[col + 1];
                if (EPI == 0) {
                    __half h2[2];
                    h2[0] = __float2half_rn(gelu_exact(v0));
                    h2[1] = __float2half_rn(gelu_exact(v1));
                    *(uint32_t*)(Ch + (size_t)row * N + col) = *(uint32_t*)h2;
                } else {
                    if (EPI == 1) { v0 = gelu_exact(v0); v1 = gelu_exact(v1); }
                    float2 o = make_float2(v0, v1);
                    *(float2*)(Cf + (size_t)row * N + col) = o;
                }
            }
        }
    }
}

// ---------------------------------------------------------------------------
// Prep kernels
// ---------------------------------------------------------------------------
__global__ void conv_kernel(const float* __restrict__ in,
                            __half* __restrict__ hi, int n4)
{
    const int i = blockIdx.x * 256 + threadIdx.x;
    if (i >= n4) return;
    float4 v = ((const float4*)in)[i];
    __half h[4];
    h[0] = __float2half_rn(v.x); h[1] = __float2half_rn(v.y);
    h[2] = __float2half_rn(v.z); h[3] = __float2half_rn(v.w);
    ((uint2*)hi)[i] = *(uint2*)h;
}

__global__ void wtr_kernel(const float* __restrict__ w, int K, int N,
                           __half* __restrict__ t)
{
    const int i = blockIdx.x * 256 + threadIdx.x;
    if (i >= N * K) return;
    const int n = i / K, k = i - n * K;
    t[i] = __float2half_rn(w[(size_t)k * N + n]);
}

// combine: cm = inv_shift(hpre)*a0 + wbuf*a1 -> fp16 (C=512, groups 57)
__global__ void combine_kernel(const float* __restrict__ hpre,
                               const float* __restrict__ wbuf,
                               const float* __restrict__ a01,
                               __half* __restrict__ oh)
{
    const int m = blockIdx.x;
    const int b = m / TPB;
    const int y = (m / Wd) % Wd;
    const int x = m % Wd;
    const int c0 = threadIdx.x * 2;
#pragma unroll
    for (int j = 0; j < 2; j++) {
        const int c = c0 + j;
        const int g = c / 57;
        const int sh = c_sh[g], sw = c_sw[g];
        const int ys = y + sh, xs = x + sw;
        float hv = 0.0f;
        if ((unsigned)ys < 56u && (unsigned)xs < 56u)
            hv = hpre[(size_t)(m + sh * Wd + sw) * CIN + c];
        const float wv = wbuf[(size_t)m * CIN + c];
        const float a0 = a01[b * CIN + c];
        const float a1 = a01[2 * CIN + b * CIN + c];
        oh[(size_t)m * CIN + c] = __float2half_rn(hv * a0 + wv * a1);
    }
}

// ---------------------------------------------------------------------------
// reduce: latency-bound -> unroll 4 to raise MLP
// ---------------------------------------------------------------------------
__global__ void reduce_kernel(const float* __restrict__ hpre,
                              const float* __restrict__ wbuf,
                              float* __restrict__ part)
{
    const int c = threadIdx.x;
    const int b = blockIdx.y;
    const int chunk = blockIdx.x;
    const int g = c / 57;
    const int sh = c_sh[g], sw = c_sw[g];
    float acc = 0.0f;
    const int m0 = b * TPB + chunk * 512;
#pragma unroll 4
    for (int it = 0; it < 512; it++) {
        const int m = m0 + it;
        const int y = (m / Wd) % Wd;
        const int x = m % Wd;
        const int ys = y + sh, xs = x + sw;
        float hv = 0.0f;
        if ((unsigned)ys < 56u && (unsigned)xs < 56u)
            hv = hpre[(size_t)(m + sh * Wd + sw) * CIN + c];
        acc += hv + wbuf[(size_t)m * CIN + c];
    }
    part[(size_t)(b * RED_CHUNKS + chunk) * CIN + c] = acc;
}

__global__ void head_kernel(const float* __restrict__ part,
                            const float* __restrict__ rw1_w,
                            const float* __restrict__ rw1_b,
                            const float* __restrict__ rw2_w,
                            const float* __restrict__ rw2_b,
                            float* __restrict__ a01)
{
    __shared__ float s_in[512];
    __shared__ float s_t1[128];
    __shared__ float s_t2[1024];
    const int tid = threadIdx.x;
    for (int b = 0; b < 2; b++) {
        float s = 0.0f;
        for (int p = 0; p < RED_CHUNKS; p++)
            s += part[(size_t)(b * RED_CHUNKS + p) * CIN + tid];
        s_in[tid] = s * (1.0f / (float)TPB);
        __syncthreads();
        if (tid < 128) {
            float acc = rw1_b[tid];
            for (int c = 0; c < 512; c++)
                acc = fmaf(s_in[c], rw1_w[c * 128 + tid], acc);
            s_t1[tid] = gelu_exact(acc);
        }
        __syncthreads();
        for (int n = tid; n < 1024; n += 512) {
            float acc = rw2_b[n];
            for (int j = 0; j < 128; j++)
                acc = fmaf(s_t1[j], rw2_w[j * 1024 + n], acc);
            s_t2[n] = acc;
        }
        __syncthreads();
        {
            const float v0 = s_t2[2 * tid];
            const float v1 = s_t2[2 * tid + 1];
            const float mx = fmaxf(v0, v1);
            const float e0 = expf(v0 - mx);
            const float e1 = expf(v1 - mx);
            const float inv = 1.0f / (e0 + e1);
            a01[b * CIN + tid]           = e0 * inv;
            a01[2 * CIN + b * CIN + tid] = e1 * inv;
        }
        __syncthreads();
    }
}

// ---------------------------------------------------------------------------
extern "C" void kernel_launch(void* const* d_in, const int* in_sizes, int n_in,
                              void* d_out, int out_size)
{
    const float* x      = (const float*)d_in[0];
    const float* fc_w   = (const float*)d_in[1];
    const float* fc_b   = (const float*)d_in[2];
    const float* fc1_w  = (const float*)d_in[3];
    const float* fc1_b  = (const float*)d_in[4];
    const float* fc2_w  = (const float*)d_in[5];
    const float* fc2_b  = (const float*)d_in[6];
    const float* rw1_w  = (const float*)d_in[7];
    const float* rw1_b  = (const float*)d_in[8];
    const float* rw2_w  = (const float*)d_in[9];
    const float* rw2_b  = (const float*)d_in[10];
    const float* proj_w = (const float*)d_in[11];
    const float* proj_b = (const float*)d_in[12];
    float* out = (float*)d_out;

    __half *xhi, *xh, *cm, *w1, *w2, *w3, *w4;
    float *hpre, *wbuf, *part, *a01;
    cudaGetSymbolAddress((void**)&xhi,  g_xhi);
    cudaGetSymbolAddress((void**)&xh,   g_xh);
    cudaGetSymbolAddress((void**)&cm,   g_cm);
    cudaGetSymbolAddress((void**)&w1, g_w1); cudaGetSymbolAddress((void**)&w2, g_w2);
    cudaGetSymbolAddress((void**)&w3, g_w3); cudaGetSymbolAddress((void**)&w4, g_w4);
    cudaGetSymbolAddress((void**)&hpre, g_hpre); cudaGetSymbolAddress((void**)&wbuf, g_wbuf);
    cudaGetSymbolAddress((void**)&part, g_part); cudaGetSymbolAddress((void**)&a01,  g_a01);

    cudaFuncSetAttribute(mma_gemm<0,0>, cudaFuncAttributeMaxDynamicSharedMemorySize, GEMM_SMEM);
    cudaFuncSetAttribute(mma_gemm<1,1>, cudaFuncAttributeMaxDynamicSharedMemorySize, GEMM_SMEM);
    cudaFuncSetAttribute(mma_gemm<1,0>, cudaFuncAttributeMaxDynamicSharedMemorySize, GEMM_SMEM);
    cudaFuncSetAttribute(mma_gemm<2,0>, cudaFuncAttributeMaxDynamicSharedMemorySize, GEMM_SMEM);

    // weights: transpose -> fp16 [N][K]
    wtr_kernel<<<(HIDN * CIN + 255) / 256, 256>>>(fc_w,  CIN,  HIDN, w1);
    wtr_kernel<<<(CIN * HIDN + 255) / 256, 256>>>(fc1_w, HIDN, CIN,  w2);
    wtr_kernel<<<(CIN * HIDN + 255) / 256, 256>>>(fc2_w, HIDN, CIN,  w3);
    wtr_kernel<<<(CIN * CIN  + 255) / 256, 256>>>(proj_w, CIN, CIN,  w4);

    // x -> fp16
    conv_kernel<<<(NTOK * CIN / 4 + 255) / 256, 256>>>(x, xhi, NTOK * CIN / 4);

    // 1) xh = gelu(x @ fc_w + b) -> fp16   [50176,1024]
    mma_gemm<0,0><<<dim3(HIDN / 256, NTOK / 128), 256, GEMM_SMEM>>>(
        xhi, w1, fc_b, HIDN, CIN, nullptr, xh);

    // 2) hpre = gelu(shift_fwd(xh) @ fc1_w + b) -> f32   (shift fused in loads)
    mma_gemm<1,1><<<dim3(CIN / 256, NTOK / 128), 256, GEMM_SMEM>>>(
        xh, w2, fc1_b, CIN, HIDN, hpre, nullptr);

    // 3) wbuf = gelu(xh @ fc2_w + b) -> f32
    mma_gemm<1,0><<<dim3(CIN / 256, NTOK / 128), 256, GEMM_SMEM>>>(
        xh, w3, fc2_b, CIN, HIDN, wbuf, nullptr);

    // 4) mean over tokens + head MLP + pairwise softmax
    reduce_kernel<<<dim3(RED_CHUNKS, 2), 512>>>(hpre, wbuf, part);
    head_kernel<<<1, 512>>>(part, rw1_w, rw1_b, rw2_w, rw2_b, a01);

    // 5) cm = h*a0 + w*a1 -> fp16
    combine_kernel<<<NTOK, 256>>>(hpre, wbuf, a01, cm);

    // 6) out = cm @ proj_w + proj_b -> f32
    mma_gemm<2,0><<<dim3(CIN / 256, NTOK / 128), 256, GEMM_SMEM>>>(
        cm, w4, proj_b, CIN, CIN, out, nullptr);
}